// round 6
// baseline (speedup 1.0000x reference)
#include <cuda_runtime.h>
#include <cuda_fp16.h>
#include <cstdint>
#include <math.h>

#define Bsz 16
#define Nn  256
#define Ll  64
#define Hh  32
#define HEe 128
#define EOo 64
#define LALPHA 0.2f

// ---------------- device scratch (no allocs allowed) ----------------
__device__ float g_h  [Bsz*Nn*Hh];
__device__ float g_rcv[Bsz*Nn*HEe];
__device__ float g_snd[Bsz*Nn*HEe];
__device__ float g_mp [4][Bsz*Nn][EOo];          // per-j-tile partial message sums
__device__ __align__(16) uint4 g_Bfrag[32*32];   // We2 fp16 in mma-fragment layout

__device__ __forceinline__ float lrelu(float v) { return fmaxf(v, LALPHA * v); }

// ---------------- K1: h0 init ----------------
__global__ void k_init(const float* __restrict__ x, const float* __restrict__ W_lin,
                       const float* __restrict__ b_lin, const float* __restrict__ W_in,
                       const float* __restrict__ b_in) {
    const int bi = blockIdx.x, b = bi >> 8, n = bi & 255;
    __shared__ float xs[Ll], ts[Ll];
    const int tid = threadIdx.x;
    xs[tid] = x[b*Ll + tid];
    __syncthreads();
    float acc = b_lin[n*Ll + tid];
    const float* wcol = W_lin + n*Ll + tid;
    #pragma unroll 16
    for (int l2 = 0; l2 < Ll; l2++) acc += xs[l2] * wcol[(size_t)l2 * (Nn*Ll)];
    ts[tid] = acc;
    __syncthreads();
    if (tid < Hh) {
        float a2 = b_in[tid];
        #pragma unroll
        for (int l = 0; l < Ll; l++) a2 += ts[l] * W_in[l*Hh + tid];
        g_h[bi*Hh + tid] = a2;
    }
}

// ---------------- K2: rcv/snd projections ----------------
__global__ void k_rs(const float* __restrict__ We1_t) {
    __shared__ float W1s[2*Hh*HEe];
    __shared__ float hs[32*Hh];
    const int tid = threadIdx.x, base = blockIdx.x * 32;
    for (int i = tid; i < 2*Hh*HEe; i += 128) W1s[i] = We1_t[i];
    for (int i = tid; i < 32*Hh;    i += 128) hs[i]  = g_h[base*Hh + i];
    __syncthreads();
    const int k = tid;
    for (int r = 0; r < 32; r++) {
        float ra = 0.f, sa = 0.f;
        #pragma unroll
        for (int hh = 0; hh < Hh; hh++) {
            float hv = hs[r*Hh + hh];
            ra += hv * W1s[hh*HEe + k];
            sa += hv * W1s[(Hh + hh)*HEe + k];
        }
        g_rcv[(size_t)(base + r)*HEe + k] = ra;
        g_snd[(size_t)(base + r)*HEe + k] = sa;
    }
}

// ---------------- K-prep: We2 [128][64] f32 -> fragment-layout fp16 ----------------
__global__ void k_prep(const float* __restrict__ We2_t) {
    const int tid = threadIdx.x;   // 256 threads
    for (int e = tid; e < 1024; e += 256) {
        const int chunk = e >> 5, lane = e & 31;
        const int ks = chunk >> 2, ntp = chunk & 3;
        const int rr = lane >> 2,  q = lane & 3;
        const int k = ks*16 + 2*q;
        uint32_t bv[4];
        #pragma unroll
        for (int s = 0; s < 2; s++) {
            const int o = (2*ntp + s)*8 + rr;
            __half2 h0 = __floats2half2_rn(We2_t[k*EOo + o],     We2_t[(k+1)*EOo + o]);
            __half2 h1 = __floats2half2_rn(We2_t[(k+8)*EOo + o], We2_t[(k+9)*EOo + o]);
            bv[2*s]   = *(uint32_t*)&h0;
            bv[2*s+1] = *(uint32_t*)&h1;
        }
        g_Bfrag[e] = make_uint4(bv[0], bv[1], bv[2], bv[3]);
    }
}

// ---------------- K3: HMMA edge kernel, i-paired + permuted-k layout ----------------
// CTA = (b, it, jt, oh): 32 i x 64 j x 32 o. grid 1024, 2 CTAs/SM.
// smem k-layout per 16-k block: positions [2q,2q+1,2q+8,2q+9] at q*4 -> one LDS.128
// yields both fragment pairs.
#define SND_STR 136
#define RCV_STR 136
#define EDGE_SMEM ((64*SND_STR + 32*RCV_STR + 64) * 4)

__global__ void __launch_bounds__(256, 2) k_edge5(const float* __restrict__ be1_t,
                                                  const float* __restrict__ be2_t) {
    extern __shared__ float sm[];
    float* snd_s = sm;                           // [64][136] permuted-k
    float* rcv_s = sm + 64*SND_STR;              // [32][136] permuted-k, +be1
    float* be2s  = sm + 64*SND_STR + 32*RCV_STR; // this CTA's 32 o's

    const int tid = threadIdx.x, w = tid >> 5, lane = tid & 31;
    const int q = lane & 3, rr = lane >> 2;
    const int bix = blockIdx.x;
    const int oh = bix & 1, jt = (bix >> 1) & 3, it = (bix >> 3) & 7, b = bix >> 6;

    // ---- register-resident B fragments: this CTA's o-half (16 uint4 = 64 regs) ----
    uint4 breg[16];
    #pragma unroll
    for (int ks = 0; ks < 8; ks++) {
        breg[ks*2 + 0] = g_Bfrag[(ks*4 + 2*oh + 0)*32 + lane];
        breg[ks*2 + 1] = g_Bfrag[(ks*4 + 2*oh + 1)*32 + lane];
    }

    // ---- stage snd j-tile (permuted-k) ----
    {
        const float4* sndg = (const float4*)(g_snd + (size_t)(b*Nn + jt*64)*HEe);
        for (int p = tid; p < 64*32; p += 256) {
            const int r = p >> 5, c4 = p & 31;
            float4 v = sndg[r*32 + c4];
            const int ks = c4 >> 2;
            const int m0 = ((c4 & 1) << 3) | (c4 & 2);   // {0,8,2,10}
            float* dst = &snd_s[r*SND_STR + ks*16 + m0];
            *(float2*)dst       = make_float2(v.x, v.y);
            *(float2*)(dst + 4) = make_float2(v.z, v.w);
        }
    }
    // ---- stage rcv i-tile (+be1, permuted-k) ----
    {
        const float4* rcvg = (const float4*)(g_rcv + (size_t)(b*Nn + it*32)*HEe);
        const float4* be1g = (const float4*)be1_t;
        for (int p = tid; p < 32*32; p += 256) {
            const int r = p >> 5, c4 = p & 31;
            float4 v = rcvg[r*32 + c4];
            float4 bb = be1g[c4];
            v.x += bb.x; v.y += bb.y; v.z += bb.z; v.w += bb.w;
            const int ks = c4 >> 2;
            const int m0 = ((c4 & 1) << 3) | (c4 & 2);
            float* dst = &rcv_s[r*RCV_STR + ks*16 + m0];
            *(float2*)dst       = make_float2(v.x, v.y);
            *(float2*)(dst + 4) = make_float2(v.z, v.w);
        }
    }
    if (tid < 32) be2s[tid] = be2_t[oh*32 + tid];
    __syncthreads();

    const int q4 = q * 4;

    // warp w handles i_loc {4w..4w+3} as 2 pairs; 64 j (4 m-tiles); 4 n-tiles (32 o)
    for (int pp = 0; pp < 2; pp++) {
        const int iloc = w*4 + pp*2;
        const float* rcvp0 = &rcv_s[iloc*RCV_STR + q4];
        const float* rcvp1 = rcvp0 + RCV_STR;

        float s[2][4][2];
        #pragma unroll
        for (int ii = 0; ii < 2; ii++)
            #pragma unroll
            for (int nt = 0; nt < 4; nt++) { s[ii][nt][0] = 0.f; s[ii][nt][1] = 0.f; }

        for (int mj = 0; mj < 4; mj++) {
            const float* spA = &snd_s[(mj*16 + rr)*SND_STR + q4];
            float acc[2][4][4];
            #pragma unroll
            for (int ii = 0; ii < 2; ii++)
                #pragma unroll
                for (int nt = 0; nt < 4; nt++)
                    { acc[ii][nt][0]=0.f; acc[ii][nt][1]=0.f; acc[ii][nt][2]=0.f; acc[ii][nt][3]=0.f; }

            #pragma unroll
            for (int ks = 0; ks < 8; ks++) {
                // one LDS.128 each: (x,y) = k-lo pair, (z,w) = k-hi pair
                float4 sA = *(const float4*)(spA + ks*16);               // row mj*16+rr
                float4 sB = *(const float4*)(spA + 8*SND_STR + ks*16);   // row +8
                float4 r0 = *(const float4*)(rcvp0 + ks*16);
                float4 r1 = *(const float4*)(rcvp1 + ks*16);

                #pragma unroll
                for (int ii = 0; ii < 2; ii++) {
                    const float4 rc = ii ? r1 : r0;
                    __half2 a0 = __floats2half2_rn(lrelu(sA.x + rc.x), lrelu(sA.y + rc.y));
                    __half2 a1 = __floats2half2_rn(lrelu(sB.x + rc.x), lrelu(sB.y + rc.y));
                    __half2 a2 = __floats2half2_rn(lrelu(sA.z + rc.z), lrelu(sA.w + rc.w));
                    __half2 a3 = __floats2half2_rn(lrelu(sB.z + rc.z), lrelu(sB.w + rc.w));
                    const uint32_t A0 = *(uint32_t*)&a0, A1 = *(uint32_t*)&a1;
                    const uint32_t A2 = *(uint32_t*)&a2, A3 = *(uint32_t*)&a3;

                    #pragma unroll
                    for (int nt = 0; nt < 4; nt++) {
                        const uint4 bb = breg[ks*2 + (nt >> 1)];
                        const uint32_t b0 = (nt & 1) ? bb.z : bb.x;
                        const uint32_t b1 = (nt & 1) ? bb.w : bb.y;
                        asm volatile("mma.sync.aligned.m16n8k16.row.col.f32.f16.f16.f32 "
                                     "{%0,%1,%2,%3}, {%4,%5,%6,%7}, {%8,%9}, {%0,%1,%2,%3};"
                                     : "+f"(acc[ii][nt][0]), "+f"(acc[ii][nt][1]),
                                       "+f"(acc[ii][nt][2]), "+f"(acc[ii][nt][3])
                                     : "r"(A0), "r"(A1), "r"(A2), "r"(A3), "r"(b0), "r"(b1));
                    }
                }
            }

            // drain: lrelu(acc + be2), sum over the 16 j-rows of this m-tile
            #pragma unroll
            for (int ii = 0; ii < 2; ii++)
                #pragma unroll
                for (int nt = 0; nt < 4; nt++) {
                    const float o0 = be2s[nt*8 + 2*q], o1 = be2s[nt*8 + 2*q + 1];
                    s[ii][nt][0] += lrelu(acc[ii][nt][0] + o0) + lrelu(acc[ii][nt][2] + o0);
                    s[ii][nt][1] += lrelu(acc[ii][nt][1] + o1) + lrelu(acc[ii][nt][3] + o1);
                }
        }

        // reduce j-sums across rr groups (lanes sharing q), store both i's
        #pragma unroll
        for (int ii = 0; ii < 2; ii++) {
            #pragma unroll
            for (int nt = 0; nt < 4; nt++)
                #pragma unroll
                for (int e = 0; e < 2; e++) {
                    float v = s[ii][nt][e];
                    v += __shfl_xor_sync(0xFFFFFFFFu, v, 4);
                    v += __shfl_xor_sync(0xFFFFFFFFu, v, 8);
                    v += __shfl_xor_sync(0xFFFFFFFFu, v, 16);
                    s[ii][nt][e] = v;
                }
            if (lane < 4) {
                const int row = b*Nn + it*32 + iloc + ii;
                float* dst = &g_mp[jt][row][oh*32];
                #pragma unroll
                for (int nt = 0; nt < 4; nt++)
                    *(float2*)&dst[nt*8 + 2*q] = make_float2(s[ii][nt][0], s[ii][nt][1]);
            }
        }
    }
}

// ---------------- K4: node update, 8 rows/block, smem-staged weights ----------------
__global__ void __launch_bounds__(256) k_node(const float* __restrict__ Wn0_t,
                                              const float* __restrict__ bn0_t,
                                              const float* __restrict__ Wn1_t,
                                              const float* __restrict__ bn1_t,
                                              float* __restrict__ out, int last) {
    __shared__ float Wn0s[(Hh + EOo) * Hh];   // 3072
    __shared__ float Wn1s[Hh * Hh];           // 1024
    __shared__ float fs[8][Hh + EOo];
    __shared__ float n0s[8][Hh];
    const int tid = threadIdx.x, r = tid >> 5, o = tid & 31;
    const int row = blockIdx.x * 8 + r;

    for (int i = tid; i < (Hh + EOo) * Hh; i += 256) Wn0s[i] = Wn0_t[i];
    for (int i = tid; i < Hh * Hh;         i += 256) Wn1s[i] = Wn1_t[i];

    fs[r][o] = g_h[(size_t)row*Hh + o];
    {
        float m0 = 0.f, m1 = 0.f;
        #pragma unroll
        for (int jtt = 0; jtt < 4; jtt++) {
            m0 += g_mp[jtt][row][o];
            m1 += g_mp[jtt][row][Hh + o];
        }
        fs[r][Hh + o]      = m0;
        fs[r][Hh + Hh + o] = m1;
    }
    __syncthreads();

    float a = bn0_t[o];
    #pragma unroll
    for (int f = 0; f < Hh + EOo; f++) a += fs[r][f] * Wn0s[f*Hh + o];
    n0s[r][o] = lrelu(a);
    __syncthreads();

    float a2 = bn1_t[o];
    #pragma unroll
    for (int f = 0; f < Hh; f++) a2 += n0s[r][f] * Wn1s[f*Hh + o];
    a2 = lrelu(a2);
    if (last) out[(size_t)row*Hh + o] = tanhf(a2);
    else      g_h[(size_t)row*Hh + o] = a2;
}

// ---------------- launch ----------------
extern "C" void kernel_launch(void* const* d_in, const int* in_sizes, int n_in,
                              void* d_out, int out_size) {
    const float* x     = (const float*)d_in[0];
    const float* W_lin = (const float*)d_in[1];
    const float* b_lin = (const float*)d_in[2];
    const float* W_in  = (const float*)d_in[3];
    const float* b_in  = (const float*)d_in[4];
    const float* We1   = (const float*)d_in[5];
    const float* be1   = (const float*)d_in[6];
    const float* We2   = (const float*)d_in[7];
    const float* be2   = (const float*)d_in[8];
    const float* Wn0   = (const float*)d_in[9];
    const float* bn0   = (const float*)d_in[10];
    const float* Wn1   = (const float*)d_in[11];
    const float* bn1   = (const float*)d_in[12];
    float* out = (float*)d_out;

    cudaFuncSetAttribute(k_edge5, cudaFuncAttributeMaxDynamicSharedMemorySize, EDGE_SMEM);

    k_init<<<Bsz*Nn, 64>>>(x, W_lin, b_lin, W_in, b_in);
    for (int t = 0; t < 3; t++) {
        k_prep<<<1, 256>>>(We2 + (size_t)t * HEe*EOo);
        k_rs  <<<(Bsz*Nn)/32, 128>>>(We1 + (size_t)t * 2*Hh*HEe);
        k_edge5<<<Bsz*8*4*2, 256, EDGE_SMEM>>>(be1 + t*HEe, be2 + t*EOo);
        k_node<<<(Bsz*Nn)/8, 256>>>(Wn0 + (size_t)t * (Hh+EOo)*Hh, bn0 + t*Hh,
                                    Wn1 + (size_t)t * Hh*Hh,        bn1 + t*Hh,
                                    out, t == 2);
    }
}

// round 8
// speedup vs baseline: 1.3195x; 1.3195x over previous
#include <cuda_runtime.h>
#include <cuda_fp16.h>
#include <cstdint>
#include <math.h>

#define Bsz 16
#define Nn  256
#define Ll  64
#define Hh  32
#define HEe 128
#define EOo 64
#define LALPHA 0.2f

// ---------------- device scratch (no allocs allowed) ----------------
__device__ float g_h  [Bsz*Nn*Hh];
__device__ float g_rcv[Bsz*Nn*HEe];
__device__ float g_snd[Bsz*Nn*HEe];
__device__ float g_mp [4][Bsz*Nn][EOo];            // per-j-tile partial message sums
__device__ __align__(16) uint4 g_Bfrag[3*1024];    // We2 fp16 fragment layout, all 3 rounds

__device__ __forceinline__ float lrelu(float v) { return fmaxf(v, LALPHA * v); }
__device__ __forceinline__ __half2 u2h(uint32_t u) { return *(__half2*)&u; }
__device__ __forceinline__ uint32_t h2u(__half2 h) { return *(uint32_t*)&h; }

// ---------------- K1: h0 init ----------------
__global__ void k_init(const float* __restrict__ x, const float* __restrict__ W_lin,
                       const float* __restrict__ b_lin, const float* __restrict__ W_in,
                       const float* __restrict__ b_in) {
    const int bi = blockIdx.x, b = bi >> 8, n = bi & 255;
    __shared__ float xs[Ll], ts[Ll];
    const int tid = threadIdx.x;
    xs[tid] = x[b*Ll + tid];
    __syncthreads();
    float acc = b_lin[n*Ll + tid];
    const float* wcol = W_lin + n*Ll + tid;
    #pragma unroll 16
    for (int l2 = 0; l2 < Ll; l2++) acc += xs[l2] * wcol[(size_t)l2 * (Nn*Ll)];
    ts[tid] = acc;
    __syncthreads();
    if (tid < Hh) {
        float a2 = b_in[tid];
        #pragma unroll
        for (int l = 0; l < Ll; l++) a2 += ts[l] * W_in[l*Hh + tid];
        g_h[bi*Hh + tid] = a2;
    }
}

// ---------------- K2: rcv/snd projections ----------------
__global__ void k_rs(const float* __restrict__ We1_t) {
    __shared__ float W1s[2*Hh*HEe];
    __shared__ float hs[32*Hh];
    const int tid = threadIdx.x, base = blockIdx.x * 32;
    for (int i = tid; i < 2*Hh*HEe; i += 128) W1s[i] = We1_t[i];
    for (int i = tid; i < 32*Hh;    i += 128) hs[i]  = g_h[base*Hh + i];
    __syncthreads();
    const int k = tid;
    for (int r = 0; r < 32; r++) {
        float ra = 0.f, sa = 0.f;
        #pragma unroll
        for (int hh = 0; hh < Hh; hh++) {
            float hv = hs[r*Hh + hh];
            ra += hv * W1s[hh*HEe + k];
            sa += hv * W1s[(Hh + hh)*HEe + k];
        }
        g_rcv[(size_t)(base + r)*HEe + k] = ra;
        g_snd[(size_t)(base + r)*HEe + k] = sa;
    }
}

// ---------------- K-prep: all 3 rounds of We2 -> fragment-layout fp16 ----------------
__global__ void k_prep(const float* __restrict__ We2) {
    const int t = blockIdx.x, tid = threadIdx.x;
    const float* We2_t = We2 + (size_t)t * HEe * EOo;
    for (int e = tid; e < 1024; e += 256) {
        const int chunk = e >> 5, lane = e & 31;
        const int ks = chunk >> 2, ntp = chunk & 3;
        const int rr = lane >> 2,  q = lane & 3;
        const int k = ks*16 + 2*q;
        uint32_t bv[4];
        #pragma unroll
        for (int s = 0; s < 2; s++) {
            const int o = (2*ntp + s)*8 + rr;
            __half2 h0 = __floats2half2_rn(We2_t[k*EOo + o],     We2_t[(k+1)*EOo + o]);
            __half2 h1 = __floats2half2_rn(We2_t[(k+8)*EOo + o], We2_t[(k+9)*EOo + o]);
            bv[2*s]   = h2u(h0);
            bv[2*s+1] = h2u(h1);
        }
        g_Bfrag[t*1024 + e] = make_uint4(bv[0], bv[1], bv[2], bv[3]);
    }
}

// ---------------- K3: HMMA edge kernel, fp16 tiles, permuted-k layout ----------------
// CTA = (b, it, jt, oh): 32 i x 64 j x 32 o. grid 1024, 2 CTAs/SM.
// smem tiles fp16, per 16-k group stored in order [2q,2q+1,2q+8,2q+9] at q*4.
// Row stride 144 halves = 288 B (≡32 mod 128 -> conflict-free 2-wf LDS.64).
#define SND_HSTR 144
#define RCV_HSTR 144
#define EDGE_SMEM (64*SND_HSTR*2 + 32*RCV_HSTR*2 + 64*4)

__global__ void __launch_bounds__(256, 2) k_edge6(int t,
                                                  const float* __restrict__ be1_t,
                                                  const float* __restrict__ be2_t) {
    extern __shared__ __align__(16) unsigned char smraw[];
    __half* snd_sh = (__half*)smraw;                         // [64][144]
    __half* rcv_sh = snd_sh + 64*SND_HSTR;                   // [32][144]
    float*  be2s   = (float*)(rcv_sh + 32*RCV_HSTR);         // [32] this CTA's o's

    const int tid = threadIdx.x, w = tid >> 5, lane = tid & 31;
    const int q = lane & 3, rr = lane >> 2;
    const int bix = blockIdx.x;
    const int oh = bix & 1, jt = (bix >> 1) & 3, it = (bix >> 3) & 7, b = bix >> 6;

    // ---- register-resident B fragments: this CTA's o-half (16 uint4 = 64 regs) ----
    // NOTE: g_Bfrag indexed in DEVICE code (device-symbol address is invalid host-side).
    const uint4* Bf = g_Bfrag + t * 1024;
    uint4 breg[16];
    #pragma unroll
    for (int ks = 0; ks < 8; ks++) {
        breg[ks*2 + 0] = Bf[(ks*4 + 2*oh + 0)*32 + lane];
        breg[ks*2 + 1] = Bf[(ks*4 + 2*oh + 1)*32 + lane];
    }

    // ---- stage snd j-tile: fp32 -> fp16, permuted-k ----
    {
        const float4* sndg = (const float4*)(g_snd + (size_t)(b*Nn + jt*64)*HEe);
        for (int p = tid; p < 64*32; p += 256) {
            const int r = p >> 5, c4 = p & 31;
            float4 v = sndg[r*32 + c4];
            const int ks = c4 >> 2, m = c4 & 3;
            const int lo = (m < 2) ? 8*m : 8*m - 14;     // {0,8,2,10}
            __half* dst = &snd_sh[r*SND_HSTR + ks*16 + lo];
            *(__half2*)dst       = __floats2half2_rn(v.x, v.y);
            *(__half2*)(dst + 4) = __floats2half2_rn(v.z, v.w);
        }
    }
    // ---- stage rcv i-tile: (+be1 in fp32) -> fp16, permuted-k ----
    {
        const float4* rcvg = (const float4*)(g_rcv + (size_t)(b*Nn + it*32)*HEe);
        const float4* be1g = (const float4*)be1_t;
        for (int p = tid; p < 32*32; p += 256) {
            const int r = p >> 5, c4 = p & 31;
            float4 v = rcvg[r*32 + c4];
            float4 bb = be1g[c4];
            v.x += bb.x; v.y += bb.y; v.z += bb.z; v.w += bb.w;
            const int ks = c4 >> 2, m = c4 & 3;
            const int lo = (m < 2) ? 8*m : 8*m - 14;
            __half* dst = &rcv_sh[r*RCV_HSTR + ks*16 + lo];
            *(__half2*)dst       = __floats2half2_rn(v.x, v.y);
            *(__half2*)(dst + 4) = __floats2half2_rn(v.z, v.w);
        }
    }
    if (tid < 32) be2s[tid] = be2_t[oh*32 + tid];
    __syncthreads();

    const __half2 alpha2 = __floats2half2_rn(LALPHA, LALPHA);
    const int q4 = q * 4;

    // warp w: i_loc {4w..4w+3}; 64 j (4 m-tiles of 16); 4 n-tiles (32 o)
    for (int ii = 0; ii < 4; ii++) {
        const int iloc = w*4 + ii;
        const __half* rcvp = &rcv_sh[iloc*RCV_HSTR + q4];

        float s[4][2];
        #pragma unroll
        for (int nt = 0; nt < 4; nt++) { s[nt][0] = 0.f; s[nt][1] = 0.f; }

        for (int mj = 0; mj < 4; mj++) {
            const __half* spA = &snd_sh[(mj*16 + rr)*SND_HSTR + q4];
            float acc[4][4];
            #pragma unroll
            for (int nt = 0; nt < 4; nt++)
                { acc[nt][0]=0.f; acc[nt][1]=0.f; acc[nt][2]=0.f; acc[nt][3]=0.f; }

            #pragma unroll
            for (int ks = 0; ks < 8; ks++) {
                const uint2 sa = *(const uint2*)(spA + ks*16);                // row r: klo, khi
                const uint2 sb = *(const uint2*)(spA + 8*SND_HSTR + ks*16);   // row r+8
                const uint2 rc = *(const uint2*)(rcvp + ks*16);

                __half2 a0 = __hadd2(u2h(sa.x), u2h(rc.x));   // row r,   k-lo
                __half2 a1 = __hadd2(u2h(sb.x), u2h(rc.x));   // row r+8, k-lo
                __half2 a2 = __hadd2(u2h(sa.y), u2h(rc.y));   // row r,   k-hi
                __half2 a3 = __hadd2(u2h(sb.y), u2h(rc.y));   // row r+8, k-hi
                a0 = __hmax2(a0, __hmul2(a0, alpha2));
                a1 = __hmax2(a1, __hmul2(a1, alpha2));
                a2 = __hmax2(a2, __hmul2(a2, alpha2));
                a3 = __hmax2(a3, __hmul2(a3, alpha2));
                const uint32_t A0 = h2u(a0), A1 = h2u(a1), A2 = h2u(a2), A3 = h2u(a3);

                #pragma unroll
                for (int nt = 0; nt < 4; nt++) {
                    const uint4 bb = breg[ks*2 + (nt >> 1)];
                    const uint32_t b0 = (nt & 1) ? bb.z : bb.x;
                    const uint32_t b1 = (nt & 1) ? bb.w : bb.y;
                    asm volatile("mma.sync.aligned.m16n8k16.row.col.f32.f16.f16.f32 "
                                 "{%0,%1,%2,%3}, {%4,%5,%6,%7}, {%8,%9}, {%0,%1,%2,%3};"
                                 : "+f"(acc[nt][0]), "+f"(acc[nt][1]),
                                   "+f"(acc[nt][2]), "+f"(acc[nt][3])
                                 : "r"(A0), "r"(A1), "r"(A2), "r"(A3), "r"(b0), "r"(b1));
                }
            }

            // drain: lrelu(acc + be2), sum over the 16 j-rows of this m-tile
            #pragma unroll
            for (int nt = 0; nt < 4; nt++) {
                const float o0 = be2s[nt*8 + 2*q], o1 = be2s[nt*8 + 2*q + 1];
                s[nt][0] += lrelu(acc[nt][0] + o0) + lrelu(acc[nt][2] + o0);
                s[nt][1] += lrelu(acc[nt][1] + o1) + lrelu(acc[nt][3] + o1);
            }
        }

        // reduce j-sums across rr groups (lanes sharing q)
        #pragma unroll
        for (int nt = 0; nt < 4; nt++)
            #pragma unroll
            for (int e = 0; e < 2; e++) {
                float v = s[nt][e];
                v += __shfl_xor_sync(0xFFFFFFFFu, v, 4);
                v += __shfl_xor_sync(0xFFFFFFFFu, v, 8);
                v += __shfl_xor_sync(0xFFFFFFFFu, v, 16);
                s[nt][e] = v;
            }
        if (lane < 4) {    // lane == q, rr == 0
            const int row = b*Nn + it*32 + iloc;
            float* dst = &g_mp[jt][row][oh*32];
            #pragma unroll
            for (int nt = 0; nt < 4; nt++)
                *(float2*)&dst[nt*8 + 2*q] = make_float2(s[nt][0], s[nt][1]);
        }
    }
}

// ---------------- K4: node update, 8 rows/block, smem-staged weights ----------------
__global__ void __launch_bounds__(256) k_node(const float* __restrict__ Wn0_t,
                                              const float* __restrict__ bn0_t,
                                              const float* __restrict__ Wn1_t,
                                              const float* __restrict__ bn1_t,
                                              float* __restrict__ out, int last) {
    __shared__ float Wn0s[(Hh + EOo) * Hh];
    __shared__ float Wn1s[Hh * Hh];
    __shared__ float fs[8][Hh + EOo];
    __shared__ float n0s[8][Hh];
    const int tid = threadIdx.x, r = tid >> 5, o = tid & 31;
    const int row = blockIdx.x * 8 + r;

    for (int i = tid; i < (Hh + EOo) * Hh; i += 256) Wn0s[i] = Wn0_t[i];
    for (int i = tid; i < Hh * Hh;         i += 256) Wn1s[i] = Wn1_t[i];

    fs[r][o] = g_h[(size_t)row*Hh + o];
    {
        float m0 = 0.f, m1 = 0.f;
        #pragma unroll
        for (int jtt = 0; jtt < 4; jtt++) {
            m0 += g_mp[jtt][row][o];
            m1 += g_mp[jtt][row][Hh + o];
        }
        fs[r][Hh + o]      = m0;
        fs[r][Hh + Hh + o] = m1;
    }
    __syncthreads();

    float a = bn0_t[o];
    #pragma unroll
    for (int f = 0; f < Hh + EOo; f++) a += fs[r][f] * Wn0s[f*Hh + o];
    n0s[r][o] = lrelu(a);
    __syncthreads();

    float a2 = bn1_t[o];
    #pragma unroll
    for (int f = 0; f < Hh; f++) a2 += n0s[r][f] * Wn1s[f*Hh + o];
    a2 = lrelu(a2);
    if (last) out[(size_t)row*Hh + o] = tanhf(a2);
    else      g_h[(size_t)row*Hh + o] = a2;
}

// ---------------- launch ----------------
extern "C" void kernel_launch(void* const* d_in, const int* in_sizes, int n_in,
                              void* d_out, int out_size) {
    const float* x     = (const float*)d_in[0];
    const float* W_lin = (const float*)d_in[1];
    const float* b_lin = (const float*)d_in[2];
    const float* W_in  = (const float*)d_in[3];
    const float* b_in  = (const float*)d_in[4];
    const float* We1   = (const float*)d_in[5];
    const float* be1   = (const float*)d_in[6];
    const float* We2   = (const float*)d_in[7];
    const float* be2   = (const float*)d_in[8];
    const float* Wn0   = (const float*)d_in[9];
    const float* bn0   = (const float*)d_in[10];
    const float* Wn1   = (const float*)d_in[11];
    const float* bn1   = (const float*)d_in[12];
    float* out = (float*)d_out;

    cudaFuncSetAttribute(k_edge6, cudaFuncAttributeMaxDynamicSharedMemorySize, EDGE_SMEM);

    k_init<<<Bsz*Nn, 64>>>(x, W_lin, b_lin, W_in, b_in);
    k_prep<<<3, 256>>>(We2);
    for (int t = 0; t < 3; t++) {
        k_rs  <<<(Bsz*Nn)/32, 128>>>(We1 + (size_t)t * 2*Hh*HEe);
        k_edge6<<<Bsz*8*4*2, 256, EDGE_SMEM>>>(t, be1 + t*HEe, be2 + t*EOo);
        k_node<<<(Bsz*Nn)/8, 256>>>(Wn0 + (size_t)t * (Hh+EOo)*Hh, bn0 + t*Hh,
                                    Wn1 + (size_t)t * Hh*Hh,        bn1 + t*Hh,
                                    out, t == 2);
    }
}

// round 9
// speedup vs baseline: 1.3540x; 1.0262x over previous
#include <cuda_runtime.h>
#include <cuda_fp16.h>
#include <cstdint>
#include <math.h>

#define Bsz 16
#define Nn  256
#define Ll  64
#define Hh  32
#define HEe 128
#define EOo 64
#define LALPHA 0.2f

// ---------------- device scratch (no allocs allowed) ----------------
__device__ float g_h  [Bsz*Nn*Hh];
__device__ float g_mp [4][Bsz*Nn][EOo];                 // per-j-tile partial message sums
__device__ __align__(16) uint32_t g_rcvh[Bsz*Nn*64];    // fp16 k-pairs, permuted, be1 folded
__device__ __align__(16) uint32_t g_sndh[Bsz*Nn*64];    // fp16 k-pairs, permuted
__device__ __align__(16) uint4 g_Bfrag[3*1024];         // We2 fp16 fragment layout, 3 rounds

__device__ __forceinline__ float lrelu(float v) { return fmaxf(v, LALPHA * v); }
__device__ __forceinline__ __half2 u2h(uint32_t u) { return *(__half2*)&u; }
__device__ __forceinline__ uint32_t h2u(__half2 h) { return *(uint32_t*)&h; }
// u32 slot for k-pair (2c,2c+1) in permuted layout: group ks=c>>3, within-group kk=2c&15
__device__ __forceinline__ int kslot(int c) { int kk = (2*c) & 15; return (c >> 3)*8 + (kk < 8 ? kk : kk - 7); }

// ---------------- K1: h0 init ----------------
__global__ void k_init(const float* __restrict__ x, const float* __restrict__ W_lin,
                       const float* __restrict__ b_lin, const float* __restrict__ W_in,
                       const float* __restrict__ b_in) {
    const int bi = blockIdx.x, b = bi >> 8, n = bi & 255;
    __shared__ float xs[Ll], ts[Ll];
    const int tid = threadIdx.x;
    xs[tid] = x[b*Ll + tid];
    __syncthreads();
    float acc = b_lin[n*Ll + tid];
    const float* wcol = W_lin + n*Ll + tid;
    #pragma unroll 16
    for (int l2 = 0; l2 < Ll; l2++) acc += xs[l2] * wcol[(size_t)l2 * (Nn*Ll)];
    ts[tid] = acc;
    __syncthreads();
    if (tid < Hh) {
        float a2 = b_in[tid];
        #pragma unroll
        for (int l = 0; l < Ll; l++) a2 += ts[l] * W_in[l*Hh + tid];
        g_h[bi*Hh + tid] = a2;
    }
}

// ---------------- K-prep: all 3 rounds of We2 -> fragment-layout fp16 ----------------
__global__ void k_prep(const float* __restrict__ We2) {
    const int t = blockIdx.x, tid = threadIdx.x;
    const float* We2_t = We2 + (size_t)t * HEe * EOo;
    for (int e = tid; e < 1024; e += 256) {
        const int chunk = e >> 5, lane = e & 31;
        const int ks = chunk >> 2, ntp = chunk & 3;
        const int rr = lane >> 2,  q = lane & 3;
        const int k = ks*16 + 2*q;
        uint32_t bv[4];
        #pragma unroll
        for (int s = 0; s < 2; s++) {
            const int o = (2*ntp + s)*8 + rr;
            __half2 h0 = __floats2half2_rn(We2_t[k*EOo + o],     We2_t[(k+1)*EOo + o]);
            __half2 h1 = __floats2half2_rn(We2_t[(k+8)*EOo + o], We2_t[(k+9)*EOo + o]);
            bv[2*s]   = h2u(h0);
            bv[2*s+1] = h2u(h1);
        }
        g_Bfrag[t*1024 + e] = make_uint4(bv[0], bv[1], bv[2], bv[3]);
    }
}

// ---------------- shared projection routine: hs2[32][32] -> rcvh/sndh fp16 tiles ----------------
__device__ __forceinline__ void project_rows(const float* hs2 /*smem [32][Hh]*/,
                                             const float* W1s /*smem [64][128]*/,
                                             const float* __restrict__ be1_t,
                                             int base, int tid) {
    const int c = tid & 63, half = tid >> 6;
    const int slot = kslot(c);
    const float b0 = half ? 0.f : be1_t[2*c];
    const float b1 = half ? 0.f : be1_t[2*c + 1];
    uint32_t* dst = half ? g_sndh : g_rcvh;
    const float2* W2 = (const float2*)(W1s + half*Hh*HEe);
    for (int r = 0; r < 32; r++) {
        float a0 = b0, a1 = b1;
        #pragma unroll
        for (int hh = 0; hh < Hh; hh++) {
            const float hv = hs2[r*Hh + hh];
            const float2 w = W2[hh*64 + c];
            a0 += hv * w.x;
            a1 += hv * w.y;
        }
        dst[(size_t)(base + r)*64 + slot] = h2u(__floats2half2_rn(a0, a1));
    }
}

// ---------------- K2a: round-0 projections from g_h ----------------
__global__ void __launch_bounds__(128) k_rs0(const float* __restrict__ We1_t,
                                             const float* __restrict__ be1_t) {
    __shared__ float W1s[2*Hh*HEe];   // 32KB
    __shared__ float hs[32*Hh];
    const int tid = threadIdx.x, base = blockIdx.x * 32;
    for (int i = tid; i < 2*Hh*HEe; i += 128) W1s[i] = We1_t[i];
    for (int i = tid; i < 32*Hh;    i += 128) hs[i]  = g_h[base*Hh + i];
    __syncthreads();
    project_rows(hs, W1s, be1_t, base, tid);
}

// ---------------- K4+K2 fused: node update (round t) + projections (round t+1) ----------------
#define NRS_SMEM ((2*Hh*HEe + (Hh+EOo)*Hh + Hh*Hh + 32*(Hh+EOo) + 32*Hh + 32*Hh) * 4)
__global__ void __launch_bounds__(128) k_noders(const float* __restrict__ Wn0_t,
                                                const float* __restrict__ bn0_t,
                                                const float* __restrict__ Wn1_t,
                                                const float* __restrict__ bn1_t,
                                                const float* __restrict__ We1_n,
                                                const float* __restrict__ be1_n) {
    extern __shared__ float dsm[];
    float* W1s  = dsm;                        // 8192
    float* Wn0s = W1s  + 2*Hh*HEe;            // 3072
    float* Wn1s = Wn0s + (Hh+EOo)*Hh;         // 1024
    float* fs   = Wn1s + Hh*Hh;               // 32*96
    float* n0s  = fs   + 32*(Hh+EOo);         // 32*32
    float* hs2  = n0s  + 32*Hh;               // 32*32
    const int tid = threadIdx.x, base = blockIdx.x * 32;

    for (int i = tid; i < 2*Hh*HEe;    i += 128) W1s[i]  = We1_n[i];
    for (int i = tid; i < (Hh+EOo)*Hh; i += 128) Wn0s[i] = Wn0_t[i];
    for (int i = tid; i < Hh*Hh;       i += 128) Wn1s[i] = Wn1_t[i];
    for (int i = tid; i < 32*Hh;       i += 128) fs[(i>>5)*96 + (i&31)] = g_h[base*Hh + i];
    for (int i = tid; i < 32*EOo;      i += 128) {
        const int r = i >> 6, o = i & 63;
        fs[r*96 + Hh + o] = g_mp[0][base+r][o] + g_mp[1][base+r][o]
                          + g_mp[2][base+r][o] + g_mp[3][base+r][o];
    }
    __syncthreads();

    const int o = tid & 31, r4 = tid >> 5;
    for (int g = 0; g < 8; g++) {
        const int r = g*4 + r4;
        float a = bn0_t[o];
        #pragma unroll
        for (int f = 0; f < Hh + EOo; f++) a += fs[r*96 + f] * Wn0s[f*Hh + o];
        n0s[r*Hh + o] = lrelu(a);
    }
    __syncthreads();
    for (int g = 0; g < 8; g++) {
        const int r = g*4 + r4;
        float a = bn1_t[o];
        #pragma unroll
        for (int f = 0; f < Hh; f++) a += n0s[r*Hh + f] * Wn1s[f*Hh + o];
        const float hv = lrelu(a);
        hs2[r*Hh + o] = hv;
        g_h[(size_t)(base + r)*Hh + o] = hv;
    }
    __syncthreads();
    project_rows(hs2, W1s, be1_n, base, tid);
}

// ---------------- K3: HMMA edge kernel, fp16 tiles (pre-permuted in gmem) ----------------
// CTA = (b, it, jt, oh): 32 i x 64 j x 32 o. grid 1024, 2 CTAs/SM.
// smem row stride 72 u32 (288B, ≡32 mod 128 -> conflict-free 2-wf LDS.64).
#define SND_HSTR 144
#define RCV_HSTR 144
#define EDGE_SMEM (64*72*4 + 32*72*4 + 32*4)

__global__ void __launch_bounds__(256, 2) k_edge6(int t, const float* __restrict__ be2_t) {
    extern __shared__ __align__(16) unsigned char smraw[];
    uint32_t* snd_u = (uint32_t*)smraw;                  // [64][72]
    uint32_t* rcv_u = snd_u + 64*72;                     // [32][72]
    float*    be2s  = (float*)(rcv_u + 32*72);           // [32]

    const int tid = threadIdx.x, w = tid >> 5, lane = tid & 31;
    const int q = lane & 3, rr = lane >> 2;
    const int bix = blockIdx.x;
    const int oh = bix & 1, jt = (bix >> 1) & 3, it = (bix >> 3) & 7, b = bix >> 6;

    // ---- register-resident B fragments (device-symbol indexed in device code) ----
    const uint4* Bf = g_Bfrag + t * 1024;
    uint4 breg[16];
    #pragma unroll
    for (int ks = 0; ks < 8; ks++) {
        breg[ks*2 + 0] = Bf[(ks*4 + 2*oh + 0)*32 + lane];
        breg[ks*2 + 1] = Bf[(ks*4 + 2*oh + 1)*32 + lane];
    }

    // ---- stage tiles: pure uint4 copies (fp16, pre-permuted) ----
    {
        const uint4* sndg = (const uint4*)(g_sndh + (size_t)(b*Nn + jt*64)*64);
        #pragma unroll
        for (int p = tid; p < 1024; p += 256) {
            const int r = p >> 4, c = p & 15;
            *(uint4*)(snd_u + r*72 + c*4) = sndg[p];
        }
        const uint4* rcvg = (const uint4*)(g_rcvh + (size_t)(b*Nn + it*32)*64);
        #pragma unroll
        for (int p = tid; p < 512; p += 256) {
            const int r = p >> 4, c = p & 15;
            *(uint4*)(rcv_u + r*72 + c*4) = rcvg[p];
        }
    }
    if (tid < 32) be2s[tid] = be2_t[oh*32 + tid];
    __syncthreads();

    const __half2 alpha2 = __floats2half2_rn(LALPHA, LALPHA);
    const int q4 = q * 4;
    const __half* snd_sh = (const __half*)snd_u;
    const __half* rcv_sh = (const __half*)rcv_u;

    for (int ii = 0; ii < 4; ii++) {
        const int iloc = w*4 + ii;
        const __half* rcvp = &rcv_sh[iloc*RCV_HSTR + q4];

        float s[4][2];
        #pragma unroll
        for (int nt = 0; nt < 4; nt++) { s[nt][0] = 0.f; s[nt][1] = 0.f; }

        for (int mj = 0; mj < 4; mj++) {
            const __half* spA = &snd_sh[(mj*16 + rr)*SND_HSTR + q4];
            float acc[4][4];
            #pragma unroll
            for (int nt = 0; nt < 4; nt++)
                { acc[nt][0]=0.f; acc[nt][1]=0.f; acc[nt][2]=0.f; acc[nt][3]=0.f; }

            #pragma unroll
            for (int ks = 0; ks < 8; ks++) {
                const uint2 sa = *(const uint2*)(spA + ks*16);
                const uint2 sb = *(const uint2*)(spA + 8*SND_HSTR + ks*16);
                const uint2 rc = *(const uint2*)(rcvp + ks*16);

                __half2 a0 = __hadd2(u2h(sa.x), u2h(rc.x));
                __half2 a1 = __hadd2(u2h(sb.x), u2h(rc.x));
                __half2 a2 = __hadd2(u2h(sa.y), u2h(rc.y));
                __half2 a3 = __hadd2(u2h(sb.y), u2h(rc.y));
                a0 = __hmax2(a0, __hmul2(a0, alpha2));
                a1 = __hmax2(a1, __hmul2(a1, alpha2));
                a2 = __hmax2(a2, __hmul2(a2, alpha2));
                a3 = __hmax2(a3, __hmul2(a3, alpha2));
                const uint32_t A0 = h2u(a0), A1 = h2u(a1), A2 = h2u(a2), A3 = h2u(a3);

                #pragma unroll
                for (int nt = 0; nt < 4; nt++) {
                    const uint4 bb = breg[ks*2 + (nt >> 1)];
                    const uint32_t b0 = (nt & 1) ? bb.z : bb.x;
                    const uint32_t b1 = (nt & 1) ? bb.w : bb.y;
                    asm volatile("mma.sync.aligned.m16n8k16.row.col.f32.f16.f16.f32 "
                                 "{%0,%1,%2,%3}, {%4,%5,%6,%7}, {%8,%9}, {%0,%1,%2,%3};"
                                 : "+f"(acc[nt][0]), "+f"(acc[nt][1]),
                                   "+f"(acc[nt][2]), "+f"(acc[nt][3])
                                 : "r"(A0), "r"(A1), "r"(A2), "r"(A3), "r"(b0), "r"(b1));
                }
            }

            #pragma unroll
            for (int nt = 0; nt < 4; nt++) {
                const float o0 = be2s[nt*8 + 2*q], o1 = be2s[nt*8 + 2*q + 1];
                s[nt][0] += lrelu(acc[nt][0] + o0) + lrelu(acc[nt][2] + o0);
                s[nt][1] += lrelu(acc[nt][1] + o1) + lrelu(acc[nt][3] + o1);
            }
        }

        #pragma unroll
        for (int nt = 0; nt < 4; nt++)
            #pragma unroll
            for (int e = 0; e < 2; e++) {
                float v = s[nt][e];
                v += __shfl_xor_sync(0xFFFFFFFFu, v, 4);
                v += __shfl_xor_sync(0xFFFFFFFFu, v, 8);
                v += __shfl_xor_sync(0xFFFFFFFFu, v, 16);
                s[nt][e] = v;
            }
        if (lane < 4) {
            const int row = b*Nn + it*32 + iloc;
            float* dst = &g_mp[jt][row][oh*32];
            #pragma unroll
            for (int nt = 0; nt < 4; nt++)
                *(float2*)&dst[nt*8 + 2*q] = make_float2(s[nt][0], s[nt][1]);
        }
    }
}

// ---------------- K4-final: node update + tanh output ----------------
__global__ void __launch_bounds__(256) k_nodef(const float* __restrict__ Wn0_t,
                                               const float* __restrict__ bn0_t,
                                               const float* __restrict__ Wn1_t,
                                               const float* __restrict__ bn1_t,
                                               float* __restrict__ out) {
    __shared__ float Wn0s[(Hh + EOo) * Hh];
    __shared__ float Wn1s[Hh * Hh];
    __shared__ float fs[8][Hh + EOo];
    __shared__ float n0s[8][Hh];
    const int tid = threadIdx.x, r = tid >> 5, o = tid & 31;
    const int row = blockIdx.x * 8 + r;

    for (int i = tid; i < (Hh + EOo) * Hh; i += 256) Wn0s[i] = Wn0_t[i];
    for (int i = tid; i < Hh * Hh;         i += 256) Wn1s[i] = Wn1_t[i];

    fs[r][o] = g_h[(size_t)row*Hh + o];
    {
        float m0 = 0.f, m1 = 0.f;
        #pragma unroll
        for (int jtt = 0; jtt < 4; jtt++) {
            m0 += g_mp[jtt][row][o];
            m1 += g_mp[jtt][row][Hh + o];
        }
        fs[r][Hh + o]      = m0;
        fs[r][Hh + Hh + o] = m1;
    }
    __syncthreads();

    float a = bn0_t[o];
    #pragma unroll
    for (int f = 0; f < Hh + EOo; f++) a += fs[r][f] * Wn0s[f*Hh + o];
    n0s[r][o] = lrelu(a);
    __syncthreads();

    float a2 = bn1_t[o];
    #pragma unroll
    for (int f = 0; f < Hh; f++) a2 += n0s[r][f] * Wn1s[f*Hh + o];
    out[(size_t)row*Hh + o] = tanhf(lrelu(a2));
}

// ---------------- launch ----------------
extern "C" void kernel_launch(void* const* d_in, const int* in_sizes, int n_in,
                              void* d_out, int out_size) {
    const float* x     = (const float*)d_in[0];
    const float* W_lin = (const float*)d_in[1];
    const float* b_lin = (const float*)d_in[2];
    const float* W_in  = (const float*)d_in[3];
    const float* b_in  = (const float*)d_in[4];
    const float* We1   = (const float*)d_in[5];
    const float* be1   = (const float*)d_in[6];
    const float* We2   = (const float*)d_in[7];
    const float* be2   = (const float*)d_in[8];
    const float* Wn0   = (const float*)d_in[9];
    const float* bn0   = (const float*)d_in[10];
    const float* Wn1   = (const float*)d_in[11];
    const float* bn1   = (const float*)d_in[12];
    float* out = (float*)d_out;

    cudaFuncSetAttribute(k_edge6,  cudaFuncAttributeMaxDynamicSharedMemorySize, EDGE_SMEM);
    cudaFuncSetAttribute(k_noders, cudaFuncAttributeMaxDynamicSharedMemorySize, NRS_SMEM);

    k_init<<<Bsz*Nn, 64>>>(x, W_lin, b_lin, W_in, b_in);
    k_prep<<<3, 256>>>(We2);
    k_rs0<<<(Bsz*Nn)/32, 128>>>(We1, be1);
    for (int t = 0; t < 3; t++) {
        k_edge6<<<Bsz*8*4*2, 256, EDGE_SMEM>>>(t, be2 + t*EOo);
        if (t < 2) {
            k_noders<<<(Bsz*Nn)/32, 128, NRS_SMEM>>>(
                Wn0 + (size_t)t * (Hh+EOo)*Hh, bn0 + t*Hh,
                Wn1 + (size_t)t * Hh*Hh,        bn1 + t*Hh,
                We1 + (size_t)(t+1) * 2*Hh*HEe, be1 + (t+1)*HEe);
        } else {
            k_nodef<<<(Bsz*Nn)/8, 256>>>(
                Wn0 + (size_t)t * (Hh+EOo)*Hh, bn0 + t*Hh,
                Wn1 + (size_t)t * Hh*Hh,        bn1 + t*Hh, out);
        }
    }
}

// round 10
// speedup vs baseline: 1.4370x; 1.0613x over previous
#include <cuda_runtime.h>
#include <cuda_fp16.h>
#include <cstdint>
#include <math.h>

#define Bsz 16
#define Nn  256
#define Ll  64
#define Hh  32
#define HEe 128
#define EOo 64
#define LALPHA 0.2f

// ---------------- device scratch (no allocs allowed) ----------------
__device__ float g_h  [Bsz*Nn*Hh];
__device__ float g_mp [4][Bsz*Nn][EOo];                 // per-j-tile partial message sums
__device__ __align__(16) uint32_t g_rcvh[Bsz*Nn*64];    // fp16 k-pairs, permuted, be1 folded
__device__ __align__(16) uint32_t g_sndh[Bsz*Nn*64];    // fp16 k-pairs, permuted
__device__ __align__(16) uint4 g_Bfrag[3*1024];         // We2 fp16 fragment layout, 3 rounds

__device__ __forceinline__ float lrelu(float v) { return fmaxf(v, LALPHA * v); }
__device__ __forceinline__ __half2 u2h(uint32_t u) { return *(__half2*)&u; }
__device__ __forceinline__ uint32_t h2u(__half2 h) { return *(uint32_t*)&h; }
// u32 slot for k-pair (2c,2c+1) in permuted layout
__device__ __forceinline__ int kslot(int c) { int kk = (2*c) & 15; return (c >> 3)*8 + (kk < 8 ? kk : kk - 7); }

// ---------------- K1: h0 init (coalesced, W_lin read once chip-wide) ----------------
// grid 64, 256 thr. Block ch owns cols [ch*256, ch*256+256) = 4 nodes, ALL 16 batches.
__global__ void __launch_bounds__(256) k_init(const float* __restrict__ x,
                                              const float* __restrict__ W_lin,
                                              const float* __restrict__ b_lin,
                                              const float* __restrict__ W_in,
                                              const float* __restrict__ b_in) {
    __shared__ float xs[Bsz*Ll];        // 1024
    __shared__ float ts[Bsz*256];       // 4096 (16 b x 256 cols)
    __shared__ float Wins[Ll*Hh];       // 2048
    __shared__ float bins[Hh];
    const int tid = threadIdx.x, ch = blockIdx.x;
    const int col = ch*256 + tid;

    for (int i = tid; i < Bsz*Ll; i += 256) xs[i] = x[i];
    for (int i = tid; i < Ll*Hh;  i += 256) Wins[i] = W_in[i];
    if (tid < Hh) bins[tid] = b_in[tid];
    __syncthreads();

    // stage 1: t[b][col] = x[b] . W_lin[:,col] + b_lin[col]
    {
        float acc[Bsz];
        const float bl = b_lin[col];
        #pragma unroll
        for (int b = 0; b < Bsz; b++) acc[b] = bl;
        for (int l2 = 0; l2 < Ll; l2++) {
            const float w = W_lin[(size_t)l2 * (Nn*Ll) + col];   // coalesced
            #pragma unroll
            for (int b = 0; b < Bsz; b++) acc[b] += xs[b*Ll + l2] * w;
        }
        #pragma unroll
        for (int b = 0; b < Bsz; b++) ts[b*256 + tid] = acc[b];
    }
    __syncthreads();

    // stage 2: h[b][node][o] = t[b][node*64..] @ W_in + b_in
    {
        const int o = tid & 31, nd = (tid >> 5) & 3, bh = tid >> 7;   // 8 b's each
        #pragma unroll
        for (int bb = 0; bb < 8; bb++) {
            const int b = bh*8 + bb;
            float a = bins[o];
            #pragma unroll
            for (int c = 0; c < Ll; c++)
                a += ts[b*256 + nd*Ll + c] * Wins[c*Hh + o];
            g_h[((size_t)b*Nn + ch*4 + nd)*Hh + o] = a;
        }
    }
}

// ---------------- projection: hs2[32][32] -> rcvh/sndh fp16 tiles (256 thr) ----------------
__device__ __forceinline__ void project_rows256(const float* hs2, const float* W1s,
                                                const float* __restrict__ be1_t,
                                                int base, int tid) {
    const int c = tid & 63, half = (tid >> 6) & 1, rh = tid >> 7;   // rows rh*16..+15
    const int slot = kslot(c);
    const float b0 = half ? 0.f : be1_t[2*c];
    const float b1 = half ? 0.f : be1_t[2*c + 1];
    uint32_t* dst = half ? g_sndh : g_rcvh;
    const float2* W2 = (const float2*)(W1s + half*Hh*HEe);
    for (int r = rh*16; r < rh*16 + 16; r++) {
        float a0 = b0, a1 = b1;
        #pragma unroll
        for (int hh = 0; hh < Hh; hh++) {
            const float hv = hs2[r*Hh + hh];
            const float2 w = W2[hh*64 + c];
            a0 += hv * w.x;
            a1 += hv * w.y;
        }
        dst[(size_t)(base + r)*64 + slot] = h2u(__floats2half2_rn(a0, a1));
    }
}

// ---------------- K2a: round-0 projections + We2 prep (merged grids) ----------------
__global__ void __launch_bounds__(256) k_rs0(const float* __restrict__ We1_t,
                                             const float* __restrict__ be1_t,
                                             const float* __restrict__ We2) {
    if (blockIdx.x >= 128) {
        // ---- We2 -> fragment-layout fp16 (3 blocks) ----
        const int t = blockIdx.x - 128, tid = threadIdx.x;
        const float* We2_t = We2 + (size_t)t * HEe * EOo;
        for (int e = tid; e < 1024; e += 256) {
            const int chunk = e >> 5, lane = e & 31;
            const int ks = chunk >> 2, ntp = chunk & 3;
            const int rr = lane >> 2,  q = lane & 3;
            const int k = ks*16 + 2*q;
            uint32_t bv[4];
            #pragma unroll
            for (int s = 0; s < 2; s++) {
                const int o = (2*ntp + s)*8 + rr;
                __half2 h0 = __floats2half2_rn(We2_t[k*EOo + o],     We2_t[(k+1)*EOo + o]);
                __half2 h1 = __floats2half2_rn(We2_t[(k+8)*EOo + o], We2_t[(k+9)*EOo + o]);
                bv[2*s]   = h2u(h0);
                bv[2*s+1] = h2u(h1);
            }
            g_Bfrag[t*1024 + e] = make_uint4(bv[0], bv[1], bv[2], bv[3]);
        }
        return;
    }
    __shared__ float W1s[2*Hh*HEe];   // 32KB
    __shared__ float hs[32*Hh];
    const int tid = threadIdx.x, base = blockIdx.x * 32;
    for (int i = tid; i < 2*Hh*HEe; i += 256) W1s[i] = We1_t[i];
    for (int i = tid; i < 32*Hh;    i += 256) hs[i]  = g_h[base*Hh + i];
    __syncthreads();
    project_rows256(hs, W1s, be1_t, base, tid);
}

// ---------------- K4+K2 fused: node update (round t) + projections (round t+1) ----------------
#define NRS_SMEM ((2*Hh*HEe + (Hh+EOo)*Hh + Hh*Hh + 32*(Hh+EOo) + 32*Hh + 32*Hh) * 4)
__global__ void __launch_bounds__(256) k_noders(const float* __restrict__ Wn0_t,
                                                const float* __restrict__ bn0_t,
                                                const float* __restrict__ Wn1_t,
                                                const float* __restrict__ bn1_t,
                                                const float* __restrict__ We1_n,
                                                const float* __restrict__ be1_n) {
    extern __shared__ float dsm[];
    float* W1s  = dsm;                        // 8192
    float* Wn0s = W1s  + 2*Hh*HEe;            // 3072
    float* Wn1s = Wn0s + (Hh+EOo)*Hh;         // 1024
    float* fs   = Wn1s + Hh*Hh;               // 32*96
    float* n0s  = fs   + 32*(Hh+EOo);         // 32*32
    float* hs2  = n0s  + 32*Hh;               // 32*32
    const int tid = threadIdx.x, base = blockIdx.x * 32;

    for (int i = tid; i < 2*Hh*HEe;    i += 256) W1s[i]  = We1_n[i];
    for (int i = tid; i < (Hh+EOo)*Hh; i += 256) Wn0s[i] = Wn0_t[i];
    for (int i = tid; i < Hh*Hh;       i += 256) Wn1s[i] = Wn1_t[i];
    for (int i = tid; i < 32*Hh;       i += 256) fs[(i>>5)*96 + (i&31)] = g_h[base*Hh + i];
    for (int i = tid; i < 32*EOo;      i += 256) {
        const int r = i >> 6, o = i & 63;
        fs[r*96 + Hh + o] = g_mp[0][base+r][o] + g_mp[1][base+r][o]
                          + g_mp[2][base+r][o] + g_mp[3][base+r][o];
    }
    __syncthreads();

    const int o = tid & 31, rg = tid >> 5;     // 8 row-groups
    #pragma unroll
    for (int g = 0; g < 4; g++) {
        const int r = g*8 + rg;
        float a = bn0_t[o];
        #pragma unroll
        for (int f = 0; f < Hh + EOo; f++) a += fs[r*96 + f] * Wn0s[f*Hh + o];
        n0s[r*Hh + o] = lrelu(a);
    }
    __syncthreads();
    #pragma unroll
    for (int g = 0; g < 4; g++) {
        const int r = g*8 + rg;
        float a = bn1_t[o];
        #pragma unroll
        for (int f = 0; f < Hh; f++) a += n0s[r*Hh + f] * Wn1s[f*Hh + o];
        const float hv = lrelu(a);
        hs2[r*Hh + o] = hv;
        g_h[(size_t)(base + r)*Hh + o] = hv;
    }
    __syncthreads();
    project_rows256(hs2, W1s, be1_n, base, tid);
}

// ---------------- K3: HMMA edge kernel (unchanged from R9) ----------------
#define SND_HSTR 144
#define RCV_HSTR 144
#define EDGE_SMEM (64*72*4 + 32*72*4 + 32*4)

__global__ void __launch_bounds__(256, 2) k_edge6(int t, const float* __restrict__ be2_t) {
    extern __shared__ __align__(16) unsigned char smraw[];
    uint32_t* snd_u = (uint32_t*)smraw;                  // [64][72]
    uint32_t* rcv_u = snd_u + 64*72;                     // [32][72]
    float*    be2s  = (float*)(rcv_u + 32*72);           // [32]

    const int tid = threadIdx.x, w = tid >> 5, lane = tid & 31;
    const int q = lane & 3, rr = lane >> 2;
    const int bix = blockIdx.x;
    const int oh = bix & 1, jt = (bix >> 1) & 3, it = (bix >> 3) & 7, b = bix >> 6;

    const uint4* Bf = g_Bfrag + t * 1024;
    uint4 breg[16];
    #pragma unroll
    for (int ks = 0; ks < 8; ks++) {
        breg[ks*2 + 0] = Bf[(ks*4 + 2*oh + 0)*32 + lane];
        breg[ks*2 + 1] = Bf[(ks*4 + 2*oh + 1)*32 + lane];
    }

    {
        const uint4* sndg = (const uint4*)(g_sndh + (size_t)(b*Nn + jt*64)*64);
        #pragma unroll
        for (int p = tid; p < 1024; p += 256) {
            const int r = p >> 4, c = p & 15;
            *(uint4*)(snd_u + r*72 + c*4) = sndg[p];
        }
        const uint4* rcvg = (const uint4*)(g_rcvh + (size_t)(b*Nn + it*32)*64);
        #pragma unroll
        for (int p = tid; p < 512; p += 256) {
            const int r = p >> 4, c = p & 15;
            *(uint4*)(rcv_u + r*72 + c*4) = rcvg[p];
        }
    }
    if (tid < 32) be2s[tid] = be2_t[oh*32 + tid];
    __syncthreads();

    const __half2 alpha2 = __floats2half2_rn(LALPHA, LALPHA);
    const int q4 = q * 4;
    const __half* snd_sh = (const __half*)snd_u;
    const __half* rcv_sh = (const __half*)rcv_u;

    for (int ii = 0; ii < 4; ii++) {
        const int iloc = w*4 + ii;
        const __half* rcvp = &rcv_sh[iloc*RCV_HSTR + q4];

        float s[4][2];
        #pragma unroll
        for (int nt = 0; nt < 4; nt++) { s[nt][0] = 0.f; s[nt][1] = 0.f; }

        for (int mj = 0; mj < 4; mj++) {
            const __half* spA = &snd_sh[(mj*16 + rr)*SND_HSTR + q4];
            float acc[4][4];
            #pragma unroll
            for (int nt = 0; nt < 4; nt++)
                { acc[nt][0]=0.f; acc[nt][1]=0.f; acc[nt][2]=0.f; acc[nt][3]=0.f; }

            #pragma unroll
            for (int ks = 0; ks < 8; ks++) {
                const uint2 sa = *(const uint2*)(spA + ks*16);
                const uint2 sb = *(const uint2*)(spA + 8*SND_HSTR + ks*16);
                const uint2 rc = *(const uint2*)(rcvp + ks*16);

                __half2 a0 = __hadd2(u2h(sa.x), u2h(rc.x));
                __half2 a1 = __hadd2(u2h(sb.x), u2h(rc.x));
                __half2 a2 = __hadd2(u2h(sa.y), u2h(rc.y));
                __half2 a3 = __hadd2(u2h(sb.y), u2h(rc.y));
                a0 = __hmax2(a0, __hmul2(a0, alpha2));
                a1 = __hmax2(a1, __hmul2(a1, alpha2));
                a2 = __hmax2(a2, __hmul2(a2, alpha2));
                a3 = __hmax2(a3, __hmul2(a3, alpha2));
                const uint32_t A0 = h2u(a0), A1 = h2u(a1), A2 = h2u(a2), A3 = h2u(a3);

                #pragma unroll
                for (int nt = 0; nt < 4; nt++) {
                    const uint4 bb = breg[ks*2 + (nt >> 1)];
                    const uint32_t b0 = (nt & 1) ? bb.z : bb.x;
                    const uint32_t b1 = (nt & 1) ? bb.w : bb.y;
                    asm volatile("mma.sync.aligned.m16n8k16.row.col.f32.f16.f16.f32 "
                                 "{%0,%1,%2,%3}, {%4,%5,%6,%7}, {%8,%9}, {%0,%1,%2,%3};"
                                 : "+f"(acc[nt][0]), "+f"(acc[nt][1]),
                                   "+f"(acc[nt][2]), "+f"(acc[nt][3])
                                 : "r"(A0), "r"(A1), "r"(A2), "r"(A3), "r"(b0), "r"(b1));
                }
            }

            #pragma unroll
            for (int nt = 0; nt < 4; nt++) {
                const float o0 = be2s[nt*8 + 2*q], o1 = be2s[nt*8 + 2*q + 1];
                s[nt][0] += lrelu(acc[nt][0] + o0) + lrelu(acc[nt][2] + o0);
                s[nt][1] += lrelu(acc[nt][1] + o1) + lrelu(acc[nt][3] + o1);
            }
        }

        #pragma unroll
        for (int nt = 0; nt < 4; nt++)
            #pragma unroll
            for (int e = 0; e < 2; e++) {
                float v = s[nt][e];
                v += __shfl_xor_sync(0xFFFFFFFFu, v, 4);
                v += __shfl_xor_sync(0xFFFFFFFFu, v, 8);
                v += __shfl_xor_sync(0xFFFFFFFFu, v, 16);
                s[nt][e] = v;
            }
        if (lane < 4) {
            const int row = b*Nn + it*32 + iloc;
            float* dst = &g_mp[jt][row][oh*32];
            #pragma unroll
            for (int nt = 0; nt < 4; nt++)
                *(float2*)&dst[nt*8 + 2*q] = make_float2(s[nt][0], s[nt][1]);
        }
    }
}

// ---------------- K4-final: node update + tanh output ----------------
__global__ void __launch_bounds__(256) k_nodef(const float* __restrict__ Wn0_t,
                                               const float* __restrict__ bn0_t,
                                               const float* __restrict__ Wn1_t,
                                               const float* __restrict__ bn1_t,
                                               float* __restrict__ out) {
    __shared__ float Wn0s[(Hh + EOo) * Hh];
    __shared__ float Wn1s[Hh * Hh];
    __shared__ float fs[8][Hh + EOo];
    __shared__ float n0s[8][Hh];
    const int tid = threadIdx.x, r = tid >> 5, o = tid & 31;
    const int row = blockIdx.x * 8 + r;

    for (int i = tid; i < (Hh + EOo) * Hh; i += 256) Wn0s[i] = Wn0_t[i];
    for (int i = tid; i < Hh * Hh;         i += 256) Wn1s[i] = Wn1_t[i];

    fs[r][o] = g_h[(size_t)row*Hh + o];
    {
        float m0 = 0.f, m1 = 0.f;
        #pragma unroll
        for (int jtt = 0; jtt < 4; jtt++) {
            m0 += g_mp[jtt][row][o];
            m1 += g_mp[jtt][row][Hh + o];
        }
        fs[r][Hh + o]      = m0;
        fs[r][Hh + Hh + o] = m1;
    }
    __syncthreads();

    float a = bn0_t[o];
    #pragma unroll
    for (int f = 0; f < Hh + EOo; f++) a += fs[r][f] * Wn0s[f*Hh + o];
    n0s[r][o] = lrelu(a);
    __syncthreads();

    float a2 = bn1_t[o];
    #pragma unroll
    for (int f = 0; f < Hh; f++) a2 += n0s[r][f] * Wn1s[f*Hh + o];
    out[(size_t)row*Hh + o] = tanhf(lrelu(a2));
}

// ---------------- launch ----------------
extern "C" void kernel_launch(void* const* d_in, const int* in_sizes, int n_in,
                              void* d_out, int out_size) {
    const float* x     = (const float*)d_in[0];
    const float* W_lin = (const float*)d_in[1];
    const float* b_lin = (const float*)d_in[2];
    const float* W_in  = (const float*)d_in[3];
    const float* b_in  = (const float*)d_in[4];
    const float* We1   = (const float*)d_in[5];
    const float* be1   = (const float*)d_in[6];
    const float* We2   = (const float*)d_in[7];
    const float* be2   = (const float*)d_in[8];
    const float* Wn0   = (const float*)d_in[9];
    const float* bn0   = (const float*)d_in[10];
    const float* Wn1   = (const float*)d_in[11];
    const float* bn1   = (const float*)d_in[12];
    float* out = (float*)d_out;

    cudaFuncSetAttribute(k_edge6,  cudaFuncAttributeMaxDynamicSharedMemorySize, EDGE_SMEM);
    cudaFuncSetAttribute(k_noders, cudaFuncAttributeMaxDynamicSharedMemorySize, NRS_SMEM);

    k_init<<<64, 256>>>(x, W_lin, b_lin, W_in, b_in);
    k_rs0<<<131, 256>>>(We1, be1, We2);
    for (int t = 0; t < 3; t++) {
        k_edge6<<<Bsz*8*4*2, 256, EDGE_SMEM>>>(t, be2 + t*EOo);
        if (t < 2) {
            k_noders<<<(Bsz*Nn)/32, 256, NRS_SMEM>>>(
                Wn0 + (size_t)t * (Hh+EOo)*Hh, bn0 + t*Hh,
                Wn1 + (size_t)t * Hh*Hh,        bn1 + t*Hh,
                We1 + (size_t)(t+1) * 2*Hh*HEe, be1 + (t+1)*HEe);
        } else {
            k_nodef<<<(Bsz*Nn)/8, 256>>>(
                Wn0 + (size_t)t * (Hh+EOo)*Hh, bn0 + t*Hh,
                Wn1 + (size_t)t * Hh*Hh,        bn1 + t*Hh, out);
        }
    }
}

// round 11
// speedup vs baseline: 1.4576x; 1.0143x over previous
#include <cuda_runtime.h>
#include <cuda_fp16.h>
#include <cstdint>
#include <math.h>

#define Bsz 16
#define Nn  256
#define Ll  64
#define Hh  32
#define HEe 128
#define EOo 64
#define LALPHA 0.2f

// ---------------- device scratch (no allocs allowed) ----------------
__device__ float g_h  [Bsz*Nn*Hh];
__device__ float g_mp [4][Bsz*Nn][EOo];                 // per-j-tile partial message sums
__device__ __align__(16) uint32_t g_rcvh[Bsz*Nn*64];    // fp16 k-pairs, permuted, be1 folded
__device__ __align__(16) uint32_t g_sndh[Bsz*Nn*64];    // fp16 k-pairs, permuted
__device__ __align__(16) uint4 g_Bfrag[3*1024];         // We2 fp16 fragment layout, 3 rounds

__device__ __forceinline__ float lrelu(float v) { return fmaxf(v, LALPHA * v); }
__device__ __forceinline__ __half2 u2h(uint32_t u) { return *(__half2*)&u; }
__device__ __forceinline__ uint32_t h2u(__half2 h) { return *(uint32_t*)&h; }
__device__ __forceinline__ int kslot(int c) { int kk = (2*c) & 15; return (c >> 3)*8 + (kk < 8 ? kk : kk - 7); }

// ---------------- K1: h0 init (coalesced, W_lin read once chip-wide) ----------------
__global__ void __launch_bounds__(256) k_init(const float* __restrict__ x,
                                              const float* __restrict__ W_lin,
                                              const float* __restrict__ b_lin,
                                              const float* __restrict__ W_in,
                                              const float* __restrict__ b_in) {
    __shared__ float xs[Bsz*Ll];
    __shared__ float ts[Bsz*256];
    __shared__ float Wins[Ll*Hh];
    __shared__ float bins[Hh];
    const int tid = threadIdx.x, ch = blockIdx.x;
    const int col = ch*256 + tid;

    for (int i = tid; i < Bsz*Ll; i += 256) xs[i] = x[i];
    for (int i = tid; i < Ll*Hh;  i += 256) Wins[i] = W_in[i];
    if (tid < Hh) bins[tid] = b_in[tid];
    __syncthreads();

    {
        float acc[Bsz];
        const float bl = b_lin[col];
        #pragma unroll
        for (int b = 0; b < Bsz; b++) acc[b] = bl;
        #pragma unroll 8
        for (int l2 = 0; l2 < Ll; l2++) {
            const float w = W_lin[(size_t)l2 * (Nn*Ll) + col];
            #pragma unroll
            for (int b = 0; b < Bsz; b++) acc[b] += xs[b*Ll + l2] * w;
        }
        #pragma unroll
        for (int b = 0; b < Bsz; b++) ts[b*256 + tid] = acc[b];
    }
    __syncthreads();

    {
        const int o = tid & 31, nd = (tid >> 5) & 3, bh = tid >> 7;
        #pragma unroll
        for (int bb = 0; bb < 8; bb++) {
            const int b = bh*8 + bb;
            float a = bins[o];
            #pragma unroll
            for (int c = 0; c < Ll; c++)
                a += ts[b*256 + nd*Ll + c] * Wins[c*Hh + o];
            g_h[((size_t)b*Nn + ch*4 + nd)*Hh + o] = a;
        }
    }
}

// ---------------- projection: weights register-hoisted, 2-row ILP ----------------
__device__ __forceinline__ void project_rows256(const float* hs2, const float* W1s,
                                                const float* __restrict__ be1_t,
                                                int base, int tid) {
    const int c = tid & 63, half = (tid >> 6) & 1, rh = tid >> 7;
    const int slot = kslot(c);
    const float b0 = half ? 0.f : be1_t[2*c];
    const float b1 = half ? 0.f : be1_t[2*c + 1];
    uint32_t* dst = half ? g_sndh : g_rcvh;
    const float2* W2 = (const float2*)(W1s + half*Hh*HEe);

    float2 wreg[Hh];                       // 64 regs, loaded ONCE
    #pragma unroll
    for (int hh = 0; hh < Hh; hh++) wreg[hh] = W2[hh*64 + c];

    #pragma unroll
    for (int rp = 0; rp < 8; rp++) {
        const int r = rh*16 + rp*2;
        float a0 = b0, a1 = b1, a2 = b0, a3 = b1;    // 4 independent chains
        #pragma unroll
        for (int hh = 0; hh < Hh; hh++) {
            const float hv0 = hs2[r*Hh + hh];
            const float hv1 = hs2[(r+1)*Hh + hh];
            a0 += hv0 * wreg[hh].x;
            a1 += hv0 * wreg[hh].y;
            a2 += hv1 * wreg[hh].x;
            a3 += hv1 * wreg[hh].y;
        }
        dst[(size_t)(base + r    )*64 + slot] = h2u(__floats2half2_rn(a0, a1));
        dst[(size_t)(base + r + 1)*64 + slot] = h2u(__floats2half2_rn(a2, a3));
    }
}

// ---------------- K2a: round-0 projections + We2 prep (merged grids) ----------------
__global__ void __launch_bounds__(256) k_rs0(const float* __restrict__ We1_t,
                                             const float* __restrict__ be1_t,
                                             const float* __restrict__ We2) {
    if (blockIdx.x >= 128) {
        const int t = blockIdx.x - 128, tid = threadIdx.x;
        const float* We2_t = We2 + (size_t)t * HEe * EOo;
        for (int e = tid; e < 1024; e += 256) {
            const int chunk = e >> 5, lane = e & 31;
            const int ks = chunk >> 2, ntp = chunk & 3;
            const int rr = lane >> 2,  q = lane & 3;
            const int k = ks*16 + 2*q;
            uint32_t bv[4];
            #pragma unroll
            for (int s = 0; s < 2; s++) {
                const int o = (2*ntp + s)*8 + rr;
                __half2 h0 = __floats2half2_rn(We2_t[k*EOo + o],     We2_t[(k+1)*EOo + o]);
                __half2 h1 = __floats2half2_rn(We2_t[(k+8)*EOo + o], We2_t[(k+9)*EOo + o]);
                bv[2*s]   = h2u(h0);
                bv[2*s+1] = h2u(h1);
            }
            g_Bfrag[t*1024 + e] = make_uint4(bv[0], bv[1], bv[2], bv[3]);
        }
        return;
    }
    __shared__ float W1s[2*Hh*HEe];
    __shared__ float hs[32*Hh];
    const int tid = threadIdx.x, base = blockIdx.x * 32;
    for (int i = tid; i < 2*Hh*HEe; i += 256) W1s[i] = We1_t[i];
    for (int i = tid; i < 32*Hh;    i += 256) hs[i]  = g_h[base*Hh + i];
    __syncthreads();
    project_rows256(hs, W1s, be1_t, base, tid);
}

// ---------------- K4+K2 fused: node update + next-round projections ----------------
#define NRS_SMEM ((2*Hh*HEe + (Hh+EOo)*Hh + Hh*Hh + 32*(Hh+EOo) + 32*Hh + 32*Hh) * 4)
__global__ void __launch_bounds__(256) k_noders(const float* __restrict__ Wn0_t,
                                                const float* __restrict__ bn0_t,
                                                const float* __restrict__ Wn1_t,
                                                const float* __restrict__ bn1_t,
                                                const float* __restrict__ We1_n,
                                                const float* __restrict__ be1_n) {
    extern __shared__ float dsm[];
    float* W1s  = dsm;
    float* Wn0s = W1s  + 2*Hh*HEe;
    float* Wn1s = Wn0s + (Hh+EOo)*Hh;
    float* fs   = Wn1s + Hh*Hh;
    float* n0s  = fs   + 32*(Hh+EOo);
    float* hs2  = n0s  + 32*Hh;
    const int tid = threadIdx.x, base = blockIdx.x * 32;

    for (int i = tid; i < 2*Hh*HEe;    i += 256) W1s[i]  = We1_n[i];
    for (int i = tid; i < (Hh+EOo)*Hh; i += 256) Wn0s[i] = Wn0_t[i];
    for (int i = tid; i < Hh*Hh;       i += 256) Wn1s[i] = Wn1_t[i];
    for (int i = tid; i < 32*Hh;       i += 256) fs[(i>>5)*96 + (i&31)] = g_h[base*Hh + i];
    for (int i = tid; i < 32*EOo;      i += 256) {
        const int r = i >> 6, o = i & 63;
        fs[r*96 + Hh + o] = g_mp[0][base+r][o] + g_mp[1][base+r][o]
                          + g_mp[2][base+r][o] + g_mp[3][base+r][o];
    }
    __syncthreads();

    const int o = tid & 31, rg = tid >> 5;
    const float bn0v = bn0_t[o], bn1v = bn1_t[o];

    // layer 0: rows {rg, rg+8} and {rg+16, rg+24}, 2 chains interleaved, weight LDS shared
    #pragma unroll
    for (int gp = 0; gp < 2; gp++) {
        const int r0 = gp*16 + rg, r1 = r0 + 8;
        float a0 = bn0v, a1 = bn0v;
        #pragma unroll
        for (int f = 0; f < Hh + EOo; f++) {
            const float wv = Wn0s[f*Hh + o];
            a0 += fs[r0*96 + f] * wv;
            a1 += fs[r1*96 + f] * wv;
        }
        n0s[r0*Hh + o] = lrelu(a0);
        n0s[r1*Hh + o] = lrelu(a1);
    }
    __syncthreads();
    #pragma unroll
    for (int gp = 0; gp < 2; gp++) {
        const int r0 = gp*16 + rg, r1 = r0 + 8;
        float a0 = bn1v, a1 = bn1v;
        #pragma unroll
        for (int f = 0; f < Hh; f++) {
            const float wv = Wn1s[f*Hh + o];
            a0 += n0s[r0*Hh + f] * wv;
            a1 += n0s[r1*Hh + f] * wv;
        }
        const float h0 = lrelu(a0), h1 = lrelu(a1);
        hs2[r0*Hh + o] = h0;  g_h[(size_t)(base + r0)*Hh + o] = h0;
        hs2[r1*Hh + o] = h1;  g_h[(size_t)(base + r1)*Hh + o] = h1;
    }
    __syncthreads();
    project_rows256(hs2, W1s, be1_n, base, tid);
}

// ---------------- K3: HMMA edge kernel (unchanged) ----------------
#define SND_HSTR 144
#define RCV_HSTR 144
#define EDGE_SMEM (64*72*4 + 32*72*4 + 32*4)

__global__ void __launch_bounds__(256, 2) k_edge6(int t, const float* __restrict__ be2_t) {
    extern __shared__ __align__(16) unsigned char smraw[];
    uint32_t* snd_u = (uint32_t*)smraw;
    uint32_t* rcv_u = snd_u + 64*72;
    float*    be2s  = (float*)(rcv_u + 32*72);

    const int tid = threadIdx.x, w = tid >> 5, lane = tid & 31;
    const int q = lane & 3, rr = lane >> 2;
    const int bix = blockIdx.x;
    const int oh = bix & 1, jt = (bix >> 1) & 3, it = (bix >> 3) & 7, b = bix >> 6;

    const uint4* Bf = g_Bfrag + t * 1024;
    uint4 breg[16];
    #pragma unroll
    for (int ks = 0; ks < 8; ks++) {
        breg[ks*2 + 0] = Bf[(ks*4 + 2*oh + 0)*32 + lane];
        breg[ks*2 + 1] = Bf[(ks*4 + 2*oh + 1)*32 + lane];
    }

    {
        const uint4* sndg = (const uint4*)(g_sndh + (size_t)(b*Nn + jt*64)*64);
        #pragma unroll
        for (int p = tid; p < 1024; p += 256) {
            const int r = p >> 4, c = p & 15;
            *(uint4*)(snd_u + r*72 + c*4) = sndg[p];
        }
        const uint4* rcvg = (const uint4*)(g_rcvh + (size_t)(b*Nn + it*32)*64);
        #pragma unroll
        for (int p = tid; p < 512; p += 256) {
            const int r = p >> 4, c = p & 15;
            *(uint4*)(rcv_u + r*72 + c*4) = rcvg[p];
        }
    }
    if (tid < 32) be2s[tid] = be2_t[oh*32 + tid];
    __syncthreads();

    const __half2 alpha2 = __floats2half2_rn(LALPHA, LALPHA);
    const int q4 = q * 4;
    const __half* snd_sh = (const __half*)snd_u;
    const __half* rcv_sh = (const __half*)rcv_u;

    for (int ii = 0; ii < 4; ii++) {
        const int iloc = w*4 + ii;
        const __half* rcvp = &rcv_sh[iloc*RCV_HSTR + q4];

        float s[4][2];
        #pragma unroll
        for (int nt = 0; nt < 4; nt++) { s[nt][0] = 0.f; s[nt][1] = 0.f; }

        for (int mj = 0; mj < 4; mj++) {
            const __half* spA = &snd_sh[(mj*16 + rr)*SND_HSTR + q4];
            float acc[4][4];
            #pragma unroll
            for (int nt = 0; nt < 4; nt++)
                { acc[nt][0]=0.f; acc[nt][1]=0.f; acc[nt][2]=0.f; acc[nt][3]=0.f; }

            #pragma unroll
            for (int ks = 0; ks < 8; ks++) {
                const uint2 sa = *(const uint2*)(spA + ks*16);
                const uint2 sb = *(const uint2*)(spA + 8*SND_HSTR + ks*16);
                const uint2 rc = *(const uint2*)(rcvp + ks*16);

                __half2 a0 = __hadd2(u2h(sa.x), u2h(rc.x));
                __half2 a1 = __hadd2(u2h(sb.x), u2h(rc.x));
                __half2 a2 = __hadd2(u2h(sa.y), u2h(rc.y));
                __half2 a3 = __hadd2(u2h(sb.y), u2h(rc.y));
                a0 = __hmax2(a0, __hmul2(a0, alpha2));
                a1 = __hmax2(a1, __hmul2(a1, alpha2));
                a2 = __hmax2(a2, __hmul2(a2, alpha2));
                a3 = __hmax2(a3, __hmul2(a3, alpha2));
                const uint32_t A0 = h2u(a0), A1 = h2u(a1), A2 = h2u(a2), A3 = h2u(a3);

                #pragma unroll
                for (int nt = 0; nt < 4; nt++) {
                    const uint4 bb = breg[ks*2 + (nt >> 1)];
                    const uint32_t b0 = (nt & 1) ? bb.z : bb.x;
                    const uint32_t b1 = (nt & 1) ? bb.w : bb.y;
                    asm volatile("mma.sync.aligned.m16n8k16.row.col.f32.f16.f16.f32 "
                                 "{%0,%1,%2,%3}, {%4,%5,%6,%7}, {%8,%9}, {%0,%1,%2,%3};"
                                 : "+f"(acc[nt][0]), "+f"(acc[nt][1]),
                                   "+f"(acc[nt][2]), "+f"(acc[nt][3])
                                 : "r"(A0), "r"(A1), "r"(A2), "r"(A3), "r"(b0), "r"(b1));
                }
            }

            #pragma unroll
            for (int nt = 0; nt < 4; nt++) {
                const float o0 = be2s[nt*8 + 2*q], o1 = be2s[nt*8 + 2*q + 1];
                s[nt][0] += lrelu(acc[nt][0] + o0) + lrelu(acc[nt][2] + o0);
                s[nt][1] += lrelu(acc[nt][1] + o1) + lrelu(acc[nt][3] + o1);
            }
        }

        #pragma unroll
        for (int nt = 0; nt < 4; nt++)
            #pragma unroll
            for (int e = 0; e < 2; e++) {
                float v = s[nt][e];
                v += __shfl_xor_sync(0xFFFFFFFFu, v, 4);
                v += __shfl_xor_sync(0xFFFFFFFFu, v, 8);
                v += __shfl_xor_sync(0xFFFFFFFFu, v, 16);
                s[nt][e] = v;
            }
        if (lane < 4) {
            const int row = b*Nn + it*32 + iloc;
            float* dst = &g_mp[jt][row][oh*32];
            #pragma unroll
            for (int nt = 0; nt < 4; nt++)
                *(float2*)&dst[nt*8 + 2*q] = make_float2(s[nt][0], s[nt][1]);
        }
    }
}

// ---------------- K4-final: node update + tanh output ----------------
__global__ void __launch_bounds__(256) k_nodef(const float* __restrict__ Wn0_t,
                                               const float* __restrict__ bn0_t,
                                               const float* __restrict__ Wn1_t,
                                               const float* __restrict__ bn1_t,
                                               float* __restrict__ out) {
    __shared__ float Wn0s[(Hh + EOo) * Hh];
    __shared__ float Wn1s[Hh * Hh];
    __shared__ float fs[8][Hh + EOo];
    __shared__ float n0s[8][Hh];
    const int tid = threadIdx.x, r = tid >> 5, o = tid & 31;
    const int row = blockIdx.x * 8 + r;

    for (int i = tid; i < (Hh + EOo) * Hh; i += 256) Wn0s[i] = Wn0_t[i];
    for (int i = tid; i < Hh * Hh;         i += 256) Wn1s[i] = Wn1_t[i];

    fs[r][o] = g_h[(size_t)row*Hh + o];
    {
        float m0 = 0.f, m1 = 0.f;
        #pragma unroll
        for (int jtt = 0; jtt < 4; jtt++) {
            m0 += g_mp[jtt][row][o];
            m1 += g_mp[jtt][row][Hh + o];
        }
        fs[r][Hh + o]      = m0;
        fs[r][Hh + Hh + o] = m1;
    }
    __syncthreads();

    float a = bn0_t[o];
    #pragma unroll
    for (int f = 0; f < Hh + EOo; f++) a += fs[r][f] * Wn0s[f*Hh + o];
    n0s[r][o] = lrelu(a);
    __syncthreads();

    float a2 = bn1_t[o];
    #pragma unroll
    for (int f = 0; f < Hh; f++) a2 += n0s[r][f] * Wn1s[f*Hh + o];
    out[(size_t)row*Hh + o] = tanhf(lrelu(a2));
}

// ---------------- launch ----------------
extern "C" void kernel_launch(void* const* d_in, const int* in_sizes, int n_in,
                              void* d_out, int out_size) {
    const float* x     = (const float*)d_in[0];
    const float* W_lin = (const float*)d_in[1];
    const float* b_lin = (const float*)d_in[2];
    const float* W_in  = (const float*)d_in[3];
    const float* b_in  = (const float*)d_in[4];
    const float* We1   = (const float*)d_in[5];
    const float* be1   = (const float*)d_in[6];
    const float* We2   = (const float*)d_in[7];
    const float* be2   = (const float*)d_in[8];
    const float* Wn0   = (const float*)d_in[9];
    const float* bn0   = (const float*)d_in[10];
    const float* Wn1   = (const float*)d_in[11];
    const float* bn1   = (const float*)d_in[12];
    float* out = (float*)d_out;

    cudaFuncSetAttribute(k_edge6,  cudaFuncAttributeMaxDynamicSharedMemorySize, EDGE_SMEM);
    cudaFuncSetAttribute(k_noders, cudaFuncAttributeMaxDynamicSharedMemorySize, NRS_SMEM);

    k_init<<<64, 256>>>(x, W_lin, b_lin, W_in, b_in);
    k_rs0<<<131, 256>>>(We1, be1, We2);
    for (int t = 0; t < 3; t++) {
        k_edge6<<<Bsz*8*4*2, 256, EDGE_SMEM>>>(t, be2 + t*EOo);
        if (t < 2) {
            k_noders<<<(Bsz*Nn)/32, 256, NRS_SMEM>>>(
                Wn0 + (size_t)t * (Hh+EOo)*Hh, bn0 + t*Hh,
                Wn1 + (size_t)t * Hh*Hh,        bn1 + t*Hh,
                We1 + (size_t)(t+1) * 2*Hh*HEe, be1 + (t+1)*HEe);
        } else {
            k_nodef<<<(Bsz*Nn)/8, 256>>>(
                Wn0 + (size_t)t * (Hh+EOo)*Hh, bn0 + t*Hh,
                Wn1 + (size_t)t * Hh*Hh,        bn1 + t*Hh, out);
        }
    }
}

// round 12
// speedup vs baseline: 1.4827x; 1.0172x over previous
#include <cuda_runtime.h>
#include <cuda_fp16.h>
#include <cstdint>
#include <math.h>

#define Bsz 16
#define Nn  256
#define Ll  64
#define Hh  32
#define HEe 128
#define EOo 64
#define LALPHA 0.2f

// ---------------- device scratch (no allocs allowed) ----------------
__device__ float g_h  [Bsz*Nn*Hh];
__device__ float g_mp [4][Bsz*Nn][EOo];                 // per-j-tile partial message sums
__device__ __align__(16) uint32_t g_rcvh[Bsz*Nn*64];    // fp16 k-pairs, permuted, be1 folded
__device__ __align__(16) uint32_t g_sndh[Bsz*Nn*64];    // fp16 k-pairs, permuted
__device__ __align__(16) uint4 g_Bfrag[3*1024];         // We2 fp16 fragment layout, 3 rounds

__device__ __forceinline__ float lrelu(float v) { return fmaxf(v, LALPHA * v); }
__device__ __forceinline__ __half2 u2h(uint32_t u) { return *(__half2*)&u; }
__device__ __forceinline__ uint32_t h2u(__half2 h) { return *(uint32_t*)&h; }
__device__ __forceinline__ int kslot(int c) { int kk = (2*c) & 15; return (c >> 3)*8 + (kk < 8 ? kk : kk - 7); }

// ---------------- K1: h0 init (coalesced, W_lin read once chip-wide) ----------------
__global__ void __launch_bounds__(256) k_init(const float* __restrict__ x,
                                              const float* __restrict__ W_lin,
                                              const float* __restrict__ b_lin,
                                              const float* __restrict__ W_in,
                                              const float* __restrict__ b_in) {
    __shared__ float xs[Bsz*Ll];
    __shared__ float ts[Bsz*256];
    __shared__ float Wins[Ll*Hh];
    __shared__ float bins[Hh];
    const int tid = threadIdx.x, ch = blockIdx.x;
    const int col = ch*256 + tid;

    for (int i = tid; i < Bsz*Ll; i += 256) xs[i] = x[i];
    for (int i = tid; i < Ll*Hh;  i += 256) Wins[i] = W_in[i];
    if (tid < Hh) bins[tid] = b_in[tid];
    __syncthreads();

    {
        float acc[Bsz];
        const float bl = b_lin[col];
        #pragma unroll
        for (int b = 0; b < Bsz; b++) acc[b] = bl;
        #pragma unroll 8
        for (int l2 = 0; l2 < Ll; l2++) {
            const float w = W_lin[(size_t)l2 * (Nn*Ll) + col];
            #pragma unroll
            for (int b = 0; b < Bsz; b++) acc[b] += xs[b*Ll + l2] * w;
        }
        #pragma unroll
        for (int b = 0; b < Bsz; b++) ts[b*256 + tid] = acc[b];
    }
    __syncthreads();

    {
        const int o = tid & 31, nd = (tid >> 5) & 3, bh = tid >> 7;
        #pragma unroll
        for (int bb = 0; bb < 8; bb++) {
            const int b = bh*8 + bb;
            float a = bins[o];
            #pragma unroll
            for (int c = 0; c < Ll; c++)
                a += ts[b*256 + nd*Ll + c] * Wins[c*Hh + o];
            g_h[((size_t)b*Nn + ch*4 + nd)*Hh + o] = a;
        }
    }
}

// ---------------- projection, 512 threads: thread=(c,half,row-quarter), 2-row pairs ----------------
__device__ __forceinline__ void project_rows512(const float* hs2, const float* W1s,
                                                const float* __restrict__ be1_t,
                                                int base, int tid) {
    const int c = tid & 63, half = (tid >> 6) & 1, rq = tid >> 7;   // rq 0..3: rows rq*8..+8
    const int slot = kslot(c);
    const float b0 = half ? 0.f : be1_t[2*c];
    const float b1 = half ? 0.f : be1_t[2*c + 1];
    uint32_t* dst = half ? g_sndh : g_rcvh;
    const float2* W2 = (const float2*)(W1s + half*Hh*HEe);

    #pragma unroll
    for (int rp = 0; rp < 4; rp++) {
        const int r = rq*8 + rp*2;
        float a0 = b0, a1 = b1, a2 = b0, a3 = b1;    // 4 independent chains
        #pragma unroll
        for (int hh = 0; hh < Hh; hh++) {
            const float2 w  = W2[hh*64 + c];
            const float hv0 = hs2[r*Hh + hh];
            const float hv1 = hs2[(r+1)*Hh + hh];
            a0 += hv0 * w.x;
            a1 += hv0 * w.y;
            a2 += hv1 * w.x;
            a3 += hv1 * w.y;
        }
        dst[(size_t)(base + r    )*64 + slot] = h2u(__floats2half2_rn(a0, a1));
        dst[(size_t)(base + r + 1)*64 + slot] = h2u(__floats2half2_rn(a2, a3));
    }
}

// ---------------- K2a: round-0 projections + We2 prep (merged grids, 512 thr) ----------------
__global__ void __launch_bounds__(512) k_rs0(const float* __restrict__ We1_t,
                                             const float* __restrict__ be1_t,
                                             const float* __restrict__ We2) {
    if (blockIdx.x >= 128) {
        const int t = blockIdx.x - 128, tid = threadIdx.x;
        const float* We2_t = We2 + (size_t)t * HEe * EOo;
        for (int e = tid; e < 1024; e += 512) {
            const int chunk = e >> 5, lane = e & 31;
            const int ks = chunk >> 2, ntp = chunk & 3;
            const int rr = lane >> 2,  q = lane & 3;
            const int k = ks*16 + 2*q;
            uint32_t bv[4];
            #pragma unroll
            for (int s = 0; s < 2; s++) {
                const int o = (2*ntp + s)*8 + rr;
                __half2 h0 = __floats2half2_rn(We2_t[k*EOo + o],     We2_t[(k+1)*EOo + o]);
                __half2 h1 = __floats2half2_rn(We2_t[(k+8)*EOo + o], We2_t[(k+9)*EOo + o]);
                bv[2*s]   = h2u(h0);
                bv[2*s+1] = h2u(h1);
            }
            g_Bfrag[t*1024 + e] = make_uint4(bv[0], bv[1], bv[2], bv[3]);
        }
        return;
    }
    __shared__ float W1s[2*Hh*HEe];
    __shared__ float hs[32*Hh];
    const int tid = threadIdx.x, base = blockIdx.x * 32;
    for (int i = tid; i < 2*Hh*HEe; i += 512) W1s[i] = We1_t[i];
    for (int i = tid; i < 32*Hh;    i += 512) hs[i]  = g_h[base*Hh + i];
    __syncthreads();
    project_rows512(hs, W1s, be1_t, base, tid);
}

// ---------------- K4+K2 fused: node update + next-round projections (512 thr) ----------------
#define NRS_SMEM ((2*Hh*HEe + (Hh+EOo)*Hh + Hh*Hh + 32*(Hh+EOo) + 32*Hh + 32*Hh) * 4)
__global__ void __launch_bounds__(512) k_noders(const float* __restrict__ Wn0_t,
                                                const float* __restrict__ bn0_t,
                                                const float* __restrict__ Wn1_t,
                                                const float* __restrict__ bn1_t,
                                                const float* __restrict__ We1_n,
                                                const float* __restrict__ be1_n) {
    extern __shared__ float dsm[];
    float* W1s  = dsm;
    float* Wn0s = W1s  + 2*Hh*HEe;
    float* Wn1s = Wn0s + (Hh+EOo)*Hh;
    float* fs   = Wn1s + Hh*Hh;
    float* n0s  = fs   + 32*(Hh+EOo);
    float* hs2  = n0s  + 32*Hh;
    const int tid = threadIdx.x, base = blockIdx.x * 32;

    for (int i = tid; i < 2*Hh*HEe;    i += 512) W1s[i]  = We1_n[i];
    for (int i = tid; i < (Hh+EOo)*Hh; i += 512) Wn0s[i] = Wn0_t[i];
    for (int i = tid; i < Hh*Hh;       i += 512) Wn1s[i] = Wn1_t[i];
    for (int i = tid; i < 32*Hh;       i += 512) fs[(i>>5)*96 + (i&31)] = g_h[base*Hh + i];
    for (int i = tid; i < 32*EOo;      i += 512) {
        const int r = i >> 6, o = i & 63;
        fs[r*96 + Hh + o] = g_mp[0][base+r][o] + g_mp[1][base+r][o]
                          + g_mp[2][base+r][o] + g_mp[3][base+r][o];
    }
    __syncthreads();

    const int o = tid & 31, rg = tid >> 5;        // rg 0..15: rows {rg, rg+16}
    const float bn0v = bn0_t[o], bn1v = bn1_t[o];

    {
        const int r0 = rg, r1 = rg + 16;
        float a0 = bn0v, a1 = bn0v;
        #pragma unroll
        for (int f = 0; f < Hh + EOo; f++) {
            const float wv = Wn0s[f*Hh + o];
            a0 += fs[r0*96 + f] * wv;
            a1 += fs[r1*96 + f] * wv;
        }
        n0s[r0*Hh + o] = lrelu(a0);
        n0s[r1*Hh + o] = lrelu(a1);
    }
    __syncthreads();
    {
        const int r0 = rg, r1 = rg + 16;
        float a0 = bn1v, a1 = bn1v;
        #pragma unroll
        for (int f = 0; f < Hh; f++) {
            const float wv = Wn1s[f*Hh + o];
            a0 += n0s[r0*Hh + f] * wv;
            a1 += n0s[r1*Hh + f] * wv;
        }
        const float h0 = lrelu(a0), h1 = lrelu(a1);
        hs2[r0*Hh + o] = h0;  g_h[(size_t)(base + r0)*Hh + o] = h0;
        hs2[r1*Hh + o] = h1;  g_h[(size_t)(base + r1)*Hh + o] = h1;
    }
    __syncthreads();
    project_rows512(hs2, W1s, be1_n, base, tid);
}

// ---------------- K3: HMMA edge kernel (unchanged) ----------------
#define SND_HSTR 144
#define RCV_HSTR 144
#define EDGE_SMEM (64*72*4 + 32*72*4 + 32*4)

__global__ void __launch_bounds__(256, 2) k_edge6(int t, const float* __restrict__ be2_t) {
    extern __shared__ __align__(16) unsigned char smraw[];
    uint32_t* snd_u = (uint32_t*)smraw;
    uint32_t* rcv_u = snd_u + 64*72;
    float*    be2s  = (float*)(rcv_u + 32*72);

    const int tid = threadIdx.x, w = tid >> 5, lane = tid & 31;
    const int q = lane & 3, rr = lane >> 2;
    const int bix = blockIdx.x;
    const int oh = bix & 1, jt = (bix >> 1) & 3, it = (bix >> 3) & 7, b = bix >> 6;

    const uint4* Bf = g_Bfrag + t * 1024;
    uint4 breg[16];
    #pragma unroll
    for (int ks = 0; ks < 8; ks++) {
        breg[ks*2 + 0] = Bf[(ks*4 + 2*oh + 0)*32 + lane];
        breg[ks*2 + 1] = Bf[(ks*4 + 2*oh + 1)*32 + lane];
    }

    {
        const uint4* sndg = (const uint4*)(g_sndh + (size_t)(b*Nn + jt*64)*64);
        #pragma unroll
        for (int p = tid; p < 1024; p += 256) {
            const int r = p >> 4, c = p & 15;
            *(uint4*)(snd_u + r*72 + c*4) = sndg[p];
        }
        const uint4* rcvg = (const uint4*)(g_rcvh + (size_t)(b*Nn + it*32)*64);
        #pragma unroll
        for (int p = tid; p < 512; p += 256) {
            const int r = p >> 4, c = p & 15;
            *(uint4*)(rcv_u + r*72 + c*4) = rcvg[p];
        }
    }
    if (tid < 32) be2s[tid] = be2_t[oh*32 + tid];
    __syncthreads();

    const __half2 alpha2 = __floats2half2_rn(LALPHA, LALPHA);
    const int q4 = q * 4;
    const __half* snd_sh = (const __half*)snd_u;
    const __half* rcv_sh = (const __half*)rcv_u;

    for (int ii = 0; ii < 4; ii++) {
        const int iloc = w*4 + ii;
        const __half* rcvp = &rcv_sh[iloc*RCV_HSTR + q4];

        float s[4][2];
        #pragma unroll
        for (int nt = 0; nt < 4; nt++) { s[nt][0] = 0.f; s[nt][1] = 0.f; }

        for (int mj = 0; mj < 4; mj++) {
            const __half* spA = &snd_sh[(mj*16 + rr)*SND_HSTR + q4];
            float acc[4][4];
            #pragma unroll
            for (int nt = 0; nt < 4; nt++)
                { acc[nt][0]=0.f; acc[nt][1]=0.f; acc[nt][2]=0.f; acc[nt][3]=0.f; }

            #pragma unroll
            for (int ks = 0; ks < 8; ks++) {
                const uint2 sa = *(const uint2*)(spA + ks*16);
                const uint2 sb = *(const uint2*)(spA + 8*SND_HSTR + ks*16);
                const uint2 rc = *(const uint2*)(rcvp + ks*16);

                __half2 a0 = __hadd2(u2h(sa.x), u2h(rc.x));
                __half2 a1 = __hadd2(u2h(sb.x), u2h(rc.x));
                __half2 a2 = __hadd2(u2h(sa.y), u2h(rc.y));
                __half2 a3 = __hadd2(u2h(sb.y), u2h(rc.y));
                a0 = __hmax2(a0, __hmul2(a0, alpha2));
                a1 = __hmax2(a1, __hmul2(a1, alpha2));
                a2 = __hmax2(a2, __hmul2(a2, alpha2));
                a3 = __hmax2(a3, __hmul2(a3, alpha2));
                const uint32_t A0 = h2u(a0), A1 = h2u(a1), A2 = h2u(a2), A3 = h2u(a3);

                #pragma unroll
                for (int nt = 0; nt < 4; nt++) {
                    const uint4 bb = breg[ks*2 + (nt >> 1)];
                    const uint32_t b0 = (nt & 1) ? bb.z : bb.x;
                    const uint32_t b1 = (nt & 1) ? bb.w : bb.y;
                    asm volatile("mma.sync.aligned.m16n8k16.row.col.f32.f16.f16.f32 "
                                 "{%0,%1,%2,%3}, {%4,%5,%6,%7}, {%8,%9}, {%0,%1,%2,%3};"
                                 : "+f"(acc[nt][0]), "+f"(acc[nt][1]),
                                   "+f"(acc[nt][2]), "+f"(acc[nt][3])
                                 : "r"(A0), "r"(A1), "r"(A2), "r"(A3), "r"(b0), "r"(b1));
                }
            }

            #pragma unroll
            for (int nt = 0; nt < 4; nt++) {
                const float o0 = be2s[nt*8 + 2*q], o1 = be2s[nt*8 + 2*q + 1];
                s[nt][0] += lrelu(acc[nt][0] + o0) + lrelu(acc[nt][2] + o0);
                s[nt][1] += lrelu(acc[nt][1] + o1) + lrelu(acc[nt][3] + o1);
            }
        }

        #pragma unroll
        for (int nt = 0; nt < 4; nt++)
            #pragma unroll
            for (int e = 0; e < 2; e++) {
                float v = s[nt][e];
                v += __shfl_xor_sync(0xFFFFFFFFu, v, 4);
                v += __shfl_xor_sync(0xFFFFFFFFu, v, 8);
                v += __shfl_xor_sync(0xFFFFFFFFu, v, 16);
                s[nt][e] = v;
            }
        if (lane < 4) {
            const int row = b*Nn + it*32 + iloc;
            float* dst = &g_mp[jt][row][oh*32];
            #pragma unroll
            for (int nt = 0; nt < 4; nt++)
                *(float2*)&dst[nt*8 + 2*q] = make_float2(s[nt][0], s[nt][1]);
        }
    }
}

// ---------------- K4-final: node update + tanh output ----------------
__global__ void __launch_bounds__(256) k_nodef(const float* __restrict__ Wn0_t,
                                               const float* __restrict__ bn0_t,
                                               const float* __restrict__ Wn1_t,
                                               const float* __restrict__ bn1_t,
                                               float* __restrict__ out) {
    __shared__ float Wn0s[(Hh + EOo) * Hh];
    __shared__ float Wn1s[Hh * Hh];
    __shared__ float fs[8][Hh + EOo];
    __shared__ float n0s[8][Hh];
    const int tid = threadIdx.x, r = tid >> 5, o = tid & 31;
    const int row = blockIdx.x * 8 + r;

    for (int i = tid; i < (Hh + EOo) * Hh; i += 256) Wn0s[i] = Wn0_t[i];
    for (int i = tid; i < Hh * Hh;         i += 256) Wn1s[i] = Wn1_t[i];

    fs[r][o] = g_h[(size_t)row*Hh + o];
    {
        float m0 = 0.f, m1 = 0.f;
        #pragma unroll
        for (int jtt = 0; jtt < 4; jtt++) {
            m0 += g_mp[jtt][row][o];
            m1 += g_mp[jtt][row][Hh + o];
        }
        fs[r][Hh + o]      = m0;
        fs[r][Hh + Hh + o] = m1;
    }
    __syncthreads();

    float a = bn0_t[o];
    #pragma unroll
    for (int f = 0; f < Hh + EOo; f++) a += fs[r][f] * Wn0s[f*Hh + o];
    n0s[r][o] = lrelu(a);
    __syncthreads();

    float a2 = bn1_t[o];
    #pragma unroll
    for (int f = 0; f < Hh; f++) a2 += n0s[r][f] * Wn1s[f*Hh + o];
    out[(size_t)row*Hh + o] = tanhf(lrelu(a2));
}

// ---------------- launch ----------------
extern "C" void kernel_launch(void* const* d_in, const int* in_sizes, int n_in,
                              void* d_out, int out_size) {
    const float* x     = (const float*)d_in[0];
    const float* W_lin = (const float*)d_in[1];
    const float* b_lin = (const float*)d_in[2];
    const float* W_in  = (const float*)d_in[3];
    const float* b_in  = (const float*)d_in[4];
    const float* We1   = (const float*)d_in[5];
    const float* be1   = (const float*)d_in[6];
    const float* We2   = (const float*)d_in[7];
    const float* be2   = (const float*)d_in[8];
    const float* Wn0   = (const float*)d_in[9];
    const float* bn0   = (const float*)d_in[10];
    const float* Wn1   = (const float*)d_in[11];
    const float* bn1   = (const float*)d_in[12];
    float* out = (float*)d_out;

    cudaFuncSetAttribute(k_edge6,  cudaFuncAttributeMaxDynamicSharedMemorySize, EDGE_SMEM);
    cudaFuncSetAttribute(k_noders, cudaFuncAttributeMaxDynamicSharedMemorySize, NRS_SMEM);

    k_init<<<64, 256>>>(x, W_lin, b_lin, W_in, b_in);
    k_rs0<<<131, 512>>>(We1, be1, We2);
    for (int t = 0; t < 3; t++) {
        k_edge6<<<Bsz*8*4*2, 256, EDGE_SMEM>>>(t, be2 + t*EOo);
        if (t < 2) {
            k_noders<<<(Bsz*Nn)/32, 512, NRS_SMEM>>>(
                Wn0 + (size_t)t * (Hh+EOo)*Hh, bn0 + t*Hh,
                Wn1 + (size_t)t * Hh*Hh,        bn1 + t*Hh,
                We1 + (size_t)(t+1) * 2*Hh*HEe, be1 + (t+1)*HEe);
        } else {
            k_nodef<<<(Bsz*Nn)/8, 256>>>(
                Wn0 + (size_t)t * (Hh+EOo)*Hh, bn0 + t*Hh,
                Wn1 + (size_t)t * Hh*Hh,        bn1 + t*Hh, out);
        }
    }
}

// round 13
// speedup vs baseline: 1.5243x; 1.0281x over previous
#include <cuda_runtime.h>
#include <cuda_fp16.h>
#include <cstdint>
#include <math.h>

#define Bsz 16
#define Nn  256
#define Ll  64
#define Hh  32
#define HEe 128
#define EOo 64
#define LALPHA 0.2f

// ---------------- device scratch (no allocs allowed) ----------------
__device__ float g_h  [Bsz*Nn*Hh];
__device__ float g_mp [4][Bsz*Nn][EOo];                 // per-j-tile partial message sums
__device__ __align__(16) uint32_t g_rcvh[Bsz*Nn*64];    // fp16 k-pairs, permuted, be1 folded
__device__ __align__(16) uint32_t g_sndh[Bsz*Nn*64];    // fp16 k-pairs, permuted
__device__ __align__(16) uint4 g_Bfrag[3*1024];         // We2 fp16 fragment layout, 3 rounds

__device__ __forceinline__ float lrelu(float v) { return fmaxf(v, LALPHA * v); }
__device__ __forceinline__ __half2 u2h(uint32_t u) { return *(__half2*)&u; }
__device__ __forceinline__ uint32_t h2u(__half2 h) { return *(uint32_t*)&h; }
__device__ __forceinline__ int kslot(int c) { int kk = (2*c) & 15; return (c >> 3)*8 + (kk < 8 ? kk : kk - 7); }

// ---------------- K1: h0 init (coalesced, W_lin read once chip-wide) ----------------
__global__ void __launch_bounds__(256) k_init(const float* __restrict__ x,
                                              const float* __restrict__ W_lin,
                                              const float* __restrict__ b_lin,
                                              const float* __restrict__ W_in,
                                              const float* __restrict__ b_in) {
    __shared__ float xs[Bsz*Ll];
    __shared__ float ts[Bsz*256];
    __shared__ float Wins[Ll*Hh];
    __shared__ float bins[Hh];
    const int tid = threadIdx.x, ch = blockIdx.x;
    const int col = ch*256 + tid;

    for (int i = tid; i < Bsz*Ll; i += 256) xs[i] = x[i];
    for (int i = tid; i < Ll*Hh;  i += 256) Wins[i] = W_in[i];
    if (tid < Hh) bins[tid] = b_in[tid];
    __syncthreads();

    {
        float acc[Bsz];
        const float bl = b_lin[col];
        #pragma unroll
        for (int b = 0; b < Bsz; b++) acc[b] = bl;
        #pragma unroll 8
        for (int l2 = 0; l2 < Ll; l2++) {
            const float w = W_lin[(size_t)l2 * (Nn*Ll) + col];
            #pragma unroll
            for (int b = 0; b < Bsz; b++) acc[b] += xs[b*Ll + l2] * w;
        }
        #pragma unroll
        for (int b = 0; b < Bsz; b++) ts[b*256 + tid] = acc[b];
    }
    __syncthreads();

    {
        const int o = tid & 31, nd = (tid >> 5) & 3, bh = tid >> 7;
        #pragma unroll
        for (int bb = 0; bb < 8; bb++) {
            const int b = bh*8 + bb;
            float a = bins[o];
            #pragma unroll
            for (int c = 0; c < Ll; c++)
                a += ts[b*256 + nd*Ll + c] * Wins[c*Hh + o];
            g_h[((size_t)b*Nn + ch*4 + nd)*Hh + o] = a;
        }
    }
}

// ---------------- projection, 128 threads, 8 rows: thread=(c,half), weights reg-hoisted from gmem ----------------
__device__ __forceinline__ void project_rows8(const float* hs2 /*[8][Hh] smem*/,
                                              const float* __restrict__ We1_t,
                                              const float* __restrict__ be1_t,
                                              int base, int tid) {
    const int c = tid & 63, half = tid >> 6;           // 128 threads
    const int slot = kslot(c);
    const float b0 = half ? 0.f : be1_t[2*c];
    const float b1 = half ? 0.f : be1_t[2*c + 1];
    uint32_t* dst = half ? g_sndh : g_rcvh;
    const float2* W2g = (const float2*)(We1_t + half*Hh*HEe);

    float2 wreg[Hh];                                   // 64 regs, L2-hot gmem, loaded once
    #pragma unroll
    for (int hh = 0; hh < Hh; hh++) wreg[hh] = W2g[hh*64 + c];

    #pragma unroll
    for (int rp = 0; rp < 4; rp++) {
        const int r = rp*2;
        float a0 = b0, a1 = b1, a2 = b0, a3 = b1;      // 4 independent chains
        #pragma unroll
        for (int hh = 0; hh < Hh; hh++) {
            const float hv0 = hs2[r*Hh + hh];
            const float hv1 = hs2[(r+1)*Hh + hh];
            a0 += hv0 * wreg[hh].x;
            a1 += hv0 * wreg[hh].y;
            a2 += hv1 * wreg[hh].x;
            a3 += hv1 * wreg[hh].y;
        }
        dst[(size_t)(base + r    )*64 + slot] = h2u(__floats2half2_rn(a0, a1));
        dst[(size_t)(base + r + 1)*64 + slot] = h2u(__floats2half2_rn(a2, a3));
    }
}

// ---------------- K2a: round-0 projections (8 rows/CTA) + We2 prep ----------------
__global__ void __launch_bounds__(128) k_rs0(const float* __restrict__ We1_t,
                                             const float* __restrict__ be1_t,
                                             const float* __restrict__ We2) {
    if (blockIdx.x >= 512) {
        const int t = blockIdx.x - 512, tid = threadIdx.x;
        const float* We2_t = We2 + (size_t)t * HEe * EOo;
        for (int e = tid; e < 1024; e += 128) {
            const int chunk = e >> 5, lane = e & 31;
            const int ks = chunk >> 2, ntp = chunk & 3;
            const int rr = lane >> 2,  q = lane & 3;
            const int k = ks*16 + 2*q;
            uint32_t bv[4];
            #pragma unroll
            for (int s = 0; s < 2; s++) {
                const int o = (2*ntp + s)*8 + rr;
                __half2 h0 = __floats2half2_rn(We2_t[k*EOo + o],     We2_t[(k+1)*EOo + o]);
                __half2 h1 = __floats2half2_rn(We2_t[(k+8)*EOo + o], We2_t[(k+9)*EOo + o]);
                bv[2*s]   = h2u(h0);
                bv[2*s+1] = h2u(h1);
            }
            g_Bfrag[t*1024 + e] = make_uint4(bv[0], bv[1], bv[2], bv[3]);
        }
        return;
    }
    __shared__ float hs[8*Hh];
    const int tid = threadIdx.x, base = blockIdx.x * 8;
    for (int i = tid; i < 8*Hh; i += 128) hs[i] = g_h[base*Hh + i];
    __syncthreads();
    project_rows8(hs, We1_t, be1_t, base, tid);
}

// ---------------- K4+K2 fused: node update + next-round projections (8 rows/CTA) ----------------
__global__ void __launch_bounds__(128) k_noders(const float* __restrict__ Wn0_t,
                                                const float* __restrict__ bn0_t,
                                                const float* __restrict__ Wn1_t,
                                                const float* __restrict__ bn1_t,
                                                const float* __restrict__ We1_n,
                                                const float* __restrict__ be1_n) {
    __shared__ float Wn0s[(Hh+EOo)*Hh];   // 3072 f
    __shared__ float Wn1s[Hh*Hh];         // 1024 f
    __shared__ float fs[8*96];
    __shared__ float n0s[8*Hh];
    __shared__ float hs2[8*Hh];
    const int tid = threadIdx.x, base = blockIdx.x * 8;

    for (int i = tid; i < (Hh+EOo)*Hh; i += 128) Wn0s[i] = Wn0_t[i];
    for (int i = tid; i < Hh*Hh;       i += 128) Wn1s[i] = Wn1_t[i];
    for (int i = tid; i < 8*Hh;        i += 128) fs[(i>>5)*96 + (i&31)] = g_h[base*Hh + i];
    for (int i = tid; i < 8*EOo;       i += 128) {
        const int r = i >> 6, o = i & 63;
        fs[r*96 + Hh + o] = g_mp[0][base+r][o] + g_mp[1][base+r][o]
                          + g_mp[2][base+r][o] + g_mp[3][base+r][o];
    }
    __syncthreads();

    const int o = tid & 31, rg = tid >> 5;       // rg 0..3: rows {rg, rg+4}
    const float bn0v = bn0_t[o], bn1v = bn1_t[o];

    {
        const int r0 = rg, r1 = rg + 4;
        float a0 = bn0v, a1 = bn0v;
        #pragma unroll
        for (int f = 0; f < Hh + EOo; f++) {
            const float wv = Wn0s[f*Hh + o];
            a0 += fs[r0*96 + f] * wv;
            a1 += fs[r1*96 + f] * wv;
        }
        n0s[r0*Hh + o] = lrelu(a0);
        n0s[r1*Hh + o] = lrelu(a1);
    }
    __syncthreads();
    {
        const int r0 = rg, r1 = rg + 4;
        float a0 = bn1v, a1 = bn1v;
        #pragma unroll
        for (int f = 0; f < Hh; f++) {
            const float wv = Wn1s[f*Hh + o];
            a0 += n0s[r0*Hh + f] * wv;
            a1 += n0s[r1*Hh + f] * wv;
        }
        const float h0 = lrelu(a0), h1 = lrelu(a1);
        hs2[r0*Hh + o] = h0;  g_h[(size_t)(base + r0)*Hh + o] = h0;
        hs2[r1*Hh + o] = h1;  g_h[(size_t)(base + r1)*Hh + o] = h1;
    }
    __syncthreads();
    project_rows8(hs2, We1_n, be1_n, base, tid);
}

// ---------------- K3: HMMA edge kernel (unchanged) ----------------
#define SND_HSTR 144
#define RCV_HSTR 144
#define EDGE_SMEM (64*72*4 + 32*72*4 + 32*4)

__global__ void __launch_bounds__(256, 2) k_edge6(int t, const float* __restrict__ be2_t) {
    extern __shared__ __align__(16) unsigned char smraw[];
    uint32_t* snd_u = (uint32_t*)smraw;
    uint32_t* rcv_u = snd_u + 64*72;
    float*    be2s  = (float*)(rcv_u + 32*72);

    const int tid = threadIdx.x, w = tid >> 5, lane = tid & 31;
    const int q = lane & 3, rr = lane >> 2;
    const int bix = blockIdx.x;
    const int oh = bix & 1, jt = (bix >> 1) & 3, it = (bix >> 3) & 7, b = bix >> 6;

    const uint4* Bf = g_Bfrag + t * 1024;
    uint4 breg[16];
    #pragma unroll
    for (int ks = 0; ks < 8; ks++) {
        breg[ks*2 + 0] = Bf[(ks*4 + 2*oh + 0)*32 + lane];
        breg[ks*2 + 1] = Bf[(ks*4 + 2*oh + 1)*32 + lane];
    }

    {
        const uint4* sndg = (const uint4*)(g_sndh + (size_t)(b*Nn + jt*64)*64);
        #pragma unroll
        for (int p = tid; p < 1024; p += 256) {
            const int r = p >> 4, c = p & 15;
            *(uint4*)(snd_u + r*72 + c*4) = sndg[p];
        }
        const uint4* rcvg = (const uint4*)(g_rcvh + (size_t)(b*Nn + it*32)*64);
        #pragma unroll
        for (int p = tid; p < 512; p += 256) {
            const int r = p >> 4, c = p & 15;
            *(uint4*)(rcv_u + r*72 + c*4) = rcvg[p];
        }
    }
    if (tid < 32) be2s[tid] = be2_t[oh*32 + tid];
    __syncthreads();

    const __half2 alpha2 = __floats2half2_rn(LALPHA, LALPHA);
    const int q4 = q * 4;
    const __half* snd_sh = (const __half*)snd_u;
    const __half* rcv_sh = (const __half*)rcv_u;

    for (int ii = 0; ii < 4; ii++) {
        const int iloc = w*4 + ii;
        const __half* rcvp = &rcv_sh[iloc*RCV_HSTR + q4];

        float s[4][2];
        #pragma unroll
        for (int nt = 0; nt < 4; nt++) { s[nt][0] = 0.f; s[nt][1] = 0.f; }

        for (int mj = 0; mj < 4; mj++) {
            const __half* spA = &snd_sh[(mj*16 + rr)*SND_HSTR + q4];
            float acc[4][4];
            #pragma unroll
            for (int nt = 0; nt < 4; nt++)
                { acc[nt][0]=0.f; acc[nt][1]=0.f; acc[nt][2]=0.f; acc[nt][3]=0.f; }

            #pragma unroll
            for (int ks = 0; ks < 8; ks++) {
                const uint2 sa = *(const uint2*)(spA + ks*16);
                const uint2 sb = *(const uint2*)(spA + 8*SND_HSTR + ks*16);
                const uint2 rc = *(const uint2*)(rcvp + ks*16);

                __half2 a0 = __hadd2(u2h(sa.x), u2h(rc.x));
                __half2 a1 = __hadd2(u2h(sb.x), u2h(rc.x));
                __half2 a2 = __hadd2(u2h(sa.y), u2h(rc.y));
                __half2 a3 = __hadd2(u2h(sb.y), u2h(rc.y));
                a0 = __hmax2(a0, __hmul2(a0, alpha2));
                a1 = __hmax2(a1, __hmul2(a1, alpha2));
                a2 = __hmax2(a2, __hmul2(a2, alpha2));
                a3 = __hmax2(a3, __hmul2(a3, alpha2));
                const uint32_t A0 = h2u(a0), A1 = h2u(a1), A2 = h2u(a2), A3 = h2u(a3);

                #pragma unroll
                for (int nt = 0; nt < 4; nt++) {
                    const uint4 bb = breg[ks*2 + (nt >> 1)];
                    const uint32_t b0 = (nt & 1) ? bb.z : bb.x;
                    const uint32_t b1 = (nt & 1) ? bb.w : bb.y;
                    asm volatile("mma.sync.aligned.m16n8k16.row.col.f32.f16.f16.f32 "
                                 "{%0,%1,%2,%3}, {%4,%5,%6,%7}, {%8,%9}, {%0,%1,%2,%3};"
                                 : "+f"(acc[nt][0]), "+f"(acc[nt][1]),
                                   "+f"(acc[nt][2]), "+f"(acc[nt][3])
                                 : "r"(A0), "r"(A1), "r"(A2), "r"(A3), "r"(b0), "r"(b1));
                }
            }

            #pragma unroll
            for (int nt = 0; nt < 4; nt++) {
                const float o0 = be2s[nt*8 + 2*q], o1 = be2s[nt*8 + 2*q + 1];
                s[nt][0] += lrelu(acc[nt][0] + o0) + lrelu(acc[nt][2] + o0);
                s[nt][1] += lrelu(acc[nt][1] + o1) + lrelu(acc[nt][3] + o1);
            }
        }

        #pragma unroll
        for (int nt = 0; nt < 4; nt++)
            #pragma unroll
            for (int e = 0; e < 2; e++) {
                float v = s[nt][e];
                v += __shfl_xor_sync(0xFFFFFFFFu, v, 4);
                v += __shfl_xor_sync(0xFFFFFFFFu, v, 8);
                v += __shfl_xor_sync(0xFFFFFFFFu, v, 16);
                s[nt][e] = v;
            }
        if (lane < 4) {
            const int row = b*Nn + it*32 + iloc;
            float* dst = &g_mp[jt][row][oh*32];
            #pragma unroll
            for (int nt = 0; nt < 4; nt++)
                *(float2*)&dst[nt*8 + 2*q] = make_float2(s[nt][0], s[nt][1]);
        }
    }
}

// ---------------- K4-final: node update + tanh output ----------------
__global__ void __launch_bounds__(256) k_nodef(const float* __restrict__ Wn0_t,
                                               const float* __restrict__ bn0_t,
                                               const float* __restrict__ Wn1_t,
                                               const float* __restrict__ bn1_t,
                                               float* __restrict__ out) {
    __shared__ float Wn0s[(Hh + EOo) * Hh];
    __shared__ float Wn1s[Hh * Hh];
    __shared__ float fs[8][Hh + EOo];
    __shared__ float n0s[8][Hh];
    const int tid = threadIdx.x, r = tid >> 5, o = tid & 31;
    const int row = blockIdx.x * 8 + r;

    for (int i = tid; i < (Hh + EOo) * Hh; i += 256) Wn0s[i] = Wn0_t[i];
    for (int i = tid; i < Hh * Hh;         i += 256) Wn1s[i] = Wn1_t[i];

    fs[r][o] = g_h[(size_t)row*Hh + o];
    {
        float m0 = 0.f, m1 = 0.f;
        #pragma unroll
        for (int jtt = 0; jtt < 4; jtt++) {
            m0 += g_mp[jtt][row][o];
            m1 += g_mp[jtt][row][Hh + o];
        }
        fs[r][Hh + o]      = m0;
        fs[r][Hh + Hh + o] = m1;
    }
    __syncthreads();

    float a = bn0_t[o];
    #pragma unroll
    for (int f = 0; f < Hh + EOo; f++) a += fs[r][f] * Wn0s[f*Hh + o];
    n0s[r][o] = lrelu(a);
    __syncthreads();

    float a2 = bn1_t[o];
    #pragma unroll
    for (int f = 0; f < Hh; f++) a2 += n0s[r][f] * Wn1s[f*Hh + o];
    out[(size_t)row*Hh + o] = tanhf(lrelu(a2));
}

// ---------------- launch ----------------
extern "C" void kernel_launch(void* const* d_in, const int* in_sizes, int n_in,
                              void* d_out, int out_size) {
    const float* x     = (const float*)d_in[0];
    const float* W_lin = (const float*)d_in[1];
    const float* b_lin = (const float*)d_in[2];
    const float* W_in  = (const float*)d_in[3];
    const float* b_in  = (const float*)d_in[4];
    const float* We1   = (const float*)d_in[5];
    const float* be1   = (const float*)d_in[6];
    const float* We2   = (const float*)d_in[7];
    const float* be2   = (const float*)d_in[8];
    const float* Wn0   = (const float*)d_in[9];
    const float* bn0   = (const float*)d_in[10];
    const float* Wn1   = (const float*)d_in[11];
    const float* bn1   = (const float*)d_in[12];
    float* out = (float*)d_out;

    cudaFuncSetAttribute(k_edge6, cudaFuncAttributeMaxDynamicSharedMemorySize, EDGE_SMEM);

    k_init<<<64, 256>>>(x, W_lin, b_lin, W_in, b_in);
    k_rs0<<<515, 128>>>(We1, be1, We2);
    for (int t = 0; t < 3; t++) {
        k_edge6<<<Bsz*8*4*2, 256, EDGE_SMEM>>>(t, be2 + t*EOo);
        if (t < 2) {
            k_noders<<<512, 128>>>(
                Wn0 + (size_t)t * (Hh+EOo)*Hh, bn0 + t*Hh,
                Wn1 + (size_t)t * Hh*Hh,        bn1 + t*Hh,
                We1 + (size_t)(t+1) * 2*Hh*HEe, be1 + (t+1)*HEe);
        } else {
            k_nodef<<<(Bsz*Nn)/8, 256>>>(
                Wn0 + (size_t)t * (Hh+EOo)*Hh, bn0 + t*Hh,
                Wn1 + (size_t)t * Hh*Hh,        bn1 + t*Hh, out);
        }
    }
}